// round 5
// baseline (speedup 1.0000x reference)
#include <cuda_runtime.h>
#include <math_constants.h>
#include <cstdint>

#define RDIM 128
#define VOL (128*128*128)
#define KH 65                       // half-spectrum planes along z (rfft)
#define CH_SPEC (KH*16384)          // float2 per spectral channel
#define NPTS 65536
#define NB 4

// ---------------- scratch (device globals; single batch, reused) ----------
// Working set per batch ~59 MB < 126 MB L2: intermediate passes stay L2-resident.
__device__ float  g_ras[3*VOL];         // rasterized normals (c, i,j,z)   25 MB
__device__ float2 g_spec[3*CH_SPEC];    // spectral (c, k,j,i), k<65       25.5 MB
__device__ float  g_scalar[2*NB];       // per batch: [0]=sum fv, [1]=phi_raw[0,0,0]

// ---------------- zeroing (per batch) ----------------
__global__ void zero_kernel(int b) {
    int i = blockIdx.x*blockDim.x + threadIdx.x;
    ((float4*)g_ras)[i] = make_float4(0.f,0.f,0.f,0.f);
    if (i < 2) g_scalar[2*b+i] = 0.f;
}

// ---------------- rasterize (trilinear scatter, 3 channels) ----------------
__global__ void raster_kernel(const float* __restrict__ V, const float* __restrict__ N) {
    int p = blockIdx.x*blockDim.x + threadIdx.x;
    float x0 = V[3*p+0]*128.f, x1 = V[3*p+1]*128.f, x2 = V[3*p+2]*128.f;
    float n0 = N[3*p+0], n1 = N[3*p+1], n2 = N[3*p+2];
    float fl0 = floorf(x0), fl1 = floorf(x1), fl2 = floorf(x2);
    int a0 = ((int)fl0)&127, a1 = ((int)fl1)&127, a2 = ((int)fl2)&127;
    int b0 = ((int)ceilf(x0))&127, b1 = ((int)ceilf(x1))&127, b2 = ((int)ceilf(x2))&127;
    float f0 = x0-fl0, f1 = x1-fl1, f2 = x2-fl2;
    #pragma unroll
    for (int c = 0; c < 8; c++) {
        int c0 = (c>>2)&1, c1 = (c>>1)&1, c2 = c&1;
        int i0 = c0 ? b0 : a0;
        int i1 = c1 ? b1 : a1;
        int i2 = c2 ? b2 : a2;
        float w = (c0 ? f0 : 1.f-f0) * (c1 ? f1 : 1.f-f1) * (c2 ? f2 : 1.f-f2);
        int idx = (i0*128 + i1)*128 + i2;
        atomicAdd(&g_ras[idx],         w*n0);
        atomicAdd(&g_ras[VOL+idx],     w*n1);
        atomicAdd(&g_ras[2*VOL+idx],   w*n2);
    }
}

// ---------------- 128-pt radix-2 DIT FFT in shared memory ----------------
// input bit-reversed -> natural order output. 64 lanes per line.
__device__ __forceinline__ void fft_line(float2* sh, int lane, float sign) {
    #pragma unroll
    for (int len = 1; len < 128; len <<= 1) {
        int j  = lane & (len-1);
        int i0 = ((lane & ~(len-1)) << 1) | j;
        int i1 = i0 + len;
        float ang = sign * CUDART_PI_F * (float)j / (float)len;
        float sw, cw; __sincosf(ang, &sw, &cw);
        float2 u = sh[i0], v = sh[i1];
        float2 t = make_float2(v.x*cw - v.y*sw, v.x*sw + v.y*cw);
        sh[i0] = make_float2(u.x+t.x, u.y+t.y);
        sh[i1] = make_float2(u.x-t.x, u.y-t.y);
        __syncthreads();
    }
}

#define BREV7(k) (__brev((unsigned)(k))>>25)

// ---- z-axis r2c: read ras (c,i,j,z), write spec (c,k,j,i), k<65 -----------
// blockIdx.y = channel. line l = j*128+i (i fast, 16 consecutive i / block).
__global__ void __launch_bounds__(1024) fft_r2c_z() {
    __shared__ float2 sh[16][RDIM];
    const float* s = g_ras  + (size_t)blockIdx.y*VOL;
    float2*      d = g_spec + (size_t)blockIdx.y*CH_SPEC;
    int l0 = blockIdx.x*16, tid = threadIdx.x;
    for (int item = tid; item < 16*128; item += 1024) {
        int ll = item>>7, z = item&127;
        int l = l0+ll;
        sh[ll][BREV7(z)] = make_float2(s[((l&127)*128 + (l>>7))*128 + z], 0.f);
    }
    __syncthreads();
    fft_line(sh[tid>>6], tid&63, -1.f);
    for (int item = tid; item < 16*KH; item += 1024) {
        int k = item>>4, ll = item&15;
        int l = l0+ll;
        d[k*16384 + (l>>7)*128 + (l&127)] = sh[ll][k];
    }
}

// ---- y-axis c2c (in place), spec (c,k,j,i): line l = k*128+i (i fast) -----
// blockIdx.y = channel (gridDim.y = 3 fwd, 1 inv).
__global__ void __launch_bounds__(1024) fft_c2c_y(float sign) {
    __shared__ float2 sh[16][RDIM];
    float2* d = g_spec + (size_t)blockIdx.y*CH_SPEC;
    int l0 = blockIdx.x*16, tid = threadIdx.x;
    for (int item = tid; item < 16*128; item += 1024) {
        int j = item>>4, ll = item&15;
        int l = l0+ll;
        sh[ll][BREV7(j)] = d[(l>>7)*16384 + j*128 + (l&127)];
    }
    __syncthreads();
    fft_line(sh[tid>>6], tid&63, sign);
    for (int item = tid; item < 16*128; item += 1024) {
        int j = item>>4, ll = item&15;
        int l = l0+ll;
        d[(l>>7)*16384 + j*128 + (l&127)] = sh[ll][j];
    }
}

// ---- fused x-axis: fwd FFT (3ch) + spectral combine + inverse FFT (1ch) --
// spec (c,k,j,i): lines along i contiguous. line l = k*128 + j.
// meshgrid 'xy' quirk: ch0 multiplier uses axis-1 idx (j), ch1 uses axis-0 (i).
#define LPF 8
__global__ void __launch_bounds__(512) fft_x_fused() {
    __shared__ float2 sh[3][LPF][RDIM];
    int l0 = blockIdx.x*LPF, tid = threadIdx.x;
    #pragma unroll
    for (int c = 0; c < 3; c++)
        for (int item = tid; item < LPF*128; item += 512) {
            int ll = item>>7, i = item&127;
            sh[c][ll][BREV7(i)] = g_spec[(size_t)c*CH_SPEC + (size_t)(l0+ll)*128 + i];
        }
    __syncthreads();
    int lane = tid&63, lg = tid>>6;
    fft_line(sh[0][lg], lane, -1.f);
    fft_line(sh[1][lg], lane, -1.f);
    fft_line(sh[2][lg], lane, -1.f);
    float2 ph[2];
    {
        int l = l0 + lg;
        int k = l>>7, j = l&127;
        const float w = 2.f*CUDART_PI_F/128.f;
        float s_j,c_j,s_k,c_k;
        sincosf(w*(float)j, &s_j, &c_j);
        sincosf(w*(float)k, &s_k, &c_k);
        float m0 = 128.f*s_j, m2 = 128.f*s_k;
        #pragma unroll
        for (int q = 0; q < 2; q++) {
            int e = lane + q*64;
            float s_i,c_i; sincosf(w*(float)e, &s_i, &c_i);
            float m1 = 128.f*s_i;
            float lap = 32768.f*((c_j-1.f)+(c_i-1.f)+(c_k-1.f));
            float2 A0=sh[0][lg][e], A1=sh[1][lg][e], A2=sh[2][lg][e];
            float dre = -(m0*A0.y + m1*A1.y + m2*A2.y);
            float dimg =  (m0*A0.x + m1*A1.x + m2*A2.x);
            float inv = 1.f/(lap + 1e-6f);
            ph[q] = make_float2(dre*inv, dimg*inv);
            if (k==0 && j==0 && e==0) ph[q] = make_float2(0.f,0.f);
        }
    }
    __syncthreads();
    sh[0][lg][BREV7(lane)]    = ph[0];
    sh[0][lg][BREV7(lane+64)] = ph[1];
    __syncthreads();
    fft_line(sh[0][lg], lane, +1.f);
    for (int item = tid; item < LPF*128; item += 512) {
        int ll = item>>7, i = item&127;
        g_spec[(size_t)(l0+ll)*128 + i] = sh[0][ll][i];
    }
}

// ---- z-axis c2r: read spec ch0 half, mirror (Hermitian), inv FFT, write out
// line l = j*128 + i (i fast). out layout (i,j,z).
__global__ void __launch_bounds__(1024) fft_c2r_z(float* __restrict__ o) {
    __shared__ float2 sh[16][RDIM];
    int l0 = blockIdx.x*16, tid = threadIdx.x;
    for (int item = tid; item < 16*KH; item += 1024) {
        int k = item>>4, ll = item&15;
        int l = l0+ll;
        float2 v = g_spec[k*16384 + (l>>7)*128 + (l&127)];
        sh[ll][BREV7(k)] = v;
        if (k >= 1 && k < 64) sh[ll][BREV7(128-k)] = make_float2(v.x, -v.y);
    }
    __syncthreads();
    fft_line(sh[tid>>6], tid&63, +1.f);
    const float scale = 1.f/(float)VOL;
    for (int item = tid; item < 16*128; item += 1024) {
        int ll = item>>7, z = item&127;
        int l = l0+ll;
        o[((l&127)*128 + (l>>7))*128 + z] = sh[ll][z].x * scale;
    }
}

// ---------------- trilinear gather at points; per-batch sums ----------------
__global__ void interp_kernel(const float* __restrict__ V, const float* __restrict__ phi, int b) {
    int p = blockIdx.x*blockDim.x + threadIdx.x;
    float x0 = V[3*p+0]*128.f, x1 = V[3*p+1]*128.f, x2 = V[3*p+2]*128.f;
    float fl0 = floorf(x0), fl1 = floorf(x1), fl2 = floorf(x2);
    int a0 = ((int)fl0)&127, a1 = ((int)fl1)&127, a2 = ((int)fl2)&127;
    int b0 = ((int)ceilf(x0))&127, b1 = ((int)ceilf(x1))&127, b2 = ((int)ceilf(x2))&127;
    float f0 = x0-fl0, f1 = x1-fl1, f2 = x2-fl2;
    float fv = 0.f;
    #pragma unroll
    for (int c = 0; c < 8; c++) {
        int c0 = (c>>2)&1, c1 = (c>>1)&1, c2 = c&1;
        int i0 = c0 ? b0 : a0;
        int i1 = c1 ? b1 : a1;
        int i2 = c2 ? b2 : a2;
        float w = (c0 ? f0 : 1.f-f0) * (c1 ? f1 : 1.f-f1) * (c2 ? f2 : 1.f-f2);
        fv += w * phi[(i0*128 + i1)*128 + i2];
    }
    #pragma unroll
    for (int o = 16; o; o >>= 1) fv += __shfl_down_sync(0xffffffffu, fv, o);
    if ((threadIdx.x & 31) == 0) atomicAdd(&g_scalar[2*b], fv);
    if (p == 0) g_scalar[2*b+1] = phi[0];
}

// ---------------- final normalize in place ----------------
__global__ void norm_kernel(float* __restrict__ phi, int b) {
    int idx = blockIdx.x*blockDim.x + threadIdx.x;
    float mean = g_scalar[2*b] * (1.f/(float)NPTS);
    float fv0  = g_scalar[2*b+1] - mean;
    float s = -0.5f / fabsf(fv0);
    phi[idx] = (phi[idx] - mean) * s;
}

// ---------------- host ----------------
extern "C" void kernel_launch(void* const* d_in, const int* in_sizes, int n_in,
                              void* d_out, int out_size) {
    (void)in_sizes; (void)n_in; (void)out_size;
    const float* V = (const float*)d_in[0];
    const float* N = (const float*)d_in[1];
    float* out = (float*)d_out;

    for (int b = 0; b < NB; b++) {
        const float* Vb = V + (size_t)b*NPTS*3;
        const float* Nb = N + (size_t)b*NPTS*3;
        float* outb = out + (size_t)b*VOL;

        zero_kernel  <<<3*VOL/4/256, 256>>>(b);
        raster_kernel<<<NPTS/256, 256>>>(Vb, Nb);

        fft_r2c_z  <<<dim3(128*128/16, 3), 1024>>>();
        fft_c2c_y  <<<dim3(KH*128/16,  3), 1024>>>(-1.f);
        fft_x_fused<<<dim3(KH*128/LPF, 1),  512>>>();
        fft_c2c_y  <<<dim3(KH*128/16,  1), 1024>>>(+1.f);
        fft_c2r_z  <<<dim3(128*128/16, 1), 1024>>>(outb);

        interp_kernel<<<NPTS/256, 256>>>(Vb, outb, b);
        norm_kernel  <<<VOL/256,  256>>>(outb, b);
    }
}

// round 6
// speedup vs baseline: 1.7277x; 1.7277x over previous
#include <cuda_runtime.h>
#include <math_constants.h>
#include <cstdint>

#define RDIM 128
#define VOL (128*128*128)
#define KH 65                       // half-spectrum planes along z (rfft)
#define CH_SPEC (KH*16384)          // float2 per spectral channel
#define NPTS 65536
#define NB 4

// smem position swizzle: spreads bit-reversed gather across banks; bijective
// within each 16-block so consecutive-index staging stays conflict-free.
#define SWZ(z) ((z) ^ (((z)>>4)&7))

// ---------------- scratch (device globals; single batch, reused) ----------
__device__ float  g_ras[3*VOL];         // rasterized normals (c, a0,a1,z)
__device__ float2 g_spec[3*CH_SPEC];    // spectral (c, k, a1, a0), k<65
__device__ float  g_scalar[2*NB];       // per batch: [0]=sum fv, [1]=phi_raw[0,0,0]

// ---------------- zeroing (per batch) ----------------
__global__ void zero_kernel(int b) {
    int i = blockIdx.x*blockDim.x + threadIdx.x;
    ((float4*)g_ras)[i] = make_float4(0.f,0.f,0.f,0.f);
    if (i < 2) g_scalar[2*b+i] = 0.f;
}

// ---------------- rasterize (trilinear scatter, 3 channels) ----------------
__global__ void raster_kernel(const float* __restrict__ V, const float* __restrict__ N) {
    int p = blockIdx.x*blockDim.x + threadIdx.x;
    float x0 = V[3*p+0]*128.f, x1 = V[3*p+1]*128.f, x2 = V[3*p+2]*128.f;
    float n0 = N[3*p+0], n1 = N[3*p+1], n2 = N[3*p+2];
    float fl0 = floorf(x0), fl1 = floorf(x1), fl2 = floorf(x2);
    int a0 = ((int)fl0)&127, a1 = ((int)fl1)&127, a2 = ((int)fl2)&127;
    int b0 = ((int)ceilf(x0))&127, b1 = ((int)ceilf(x1))&127, b2 = ((int)ceilf(x2))&127;
    float f0 = x0-fl0, f1 = x1-fl1, f2 = x2-fl2;
    #pragma unroll
    for (int c = 0; c < 8; c++) {
        int c0 = (c>>2)&1, c1 = (c>>1)&1, c2 = c&1;
        int i0 = c0 ? b0 : a0;
        int i1 = c1 ? b1 : a1;
        int i2 = c2 ? b2 : a2;
        float w = (c0 ? f0 : 1.f-f0) * (c1 ? f1 : 1.f-f1) * (c2 ? f2 : 1.f-f2);
        int idx = (i0*128 + i1)*128 + i2;
        atomicAdd(&g_ras[idx],         w*n0);
        atomicAdd(&g_ras[VOL+idx],     w*n1);
        atomicAdd(&g_ras[2*VOL+idx],   w*n2);
    }
}

// ---------------- register-resident 128-pt FFT (one warp per line) --------
__device__ __forceinline__ float2 cadd(float2 a, float2 b){return make_float2(a.x+b.x, a.y+b.y);}
__device__ __forceinline__ float2 csub(float2 a, float2 b){return make_float2(a.x-b.x, a.y-b.y);}
__device__ __forceinline__ float2 cmul(float2 a, float2 b){return make_float2(a.x*b.x-a.y*b.y, a.x*b.y+a.y*b.x);}

// twiddles depend only on lane: tw[s] = exp(i*sign*pi*(lane&(len-1))/len)
__device__ __forceinline__ void make_tw(float2 tw[7], int lane, float sign) {
    tw[0] = make_float2(1.f, 0.f);
    #pragma unroll
    for (int s = 1; s <= 4; s++) {
        int len = 1<<s;
        float ang = sign*CUDART_PI_F*(float)(lane&(len-1))/(float)len;
        __sincosf(ang, &tw[s].y, &tw[s].x);
    }
    float ang = sign*CUDART_PI_F*(float)lane/32.f;
    __sincosf(ang, &tw[5].y, &tw[5].x);
    ang = sign*CUDART_PI_F*(float)lane/64.f;
    __sincosf(ang, &tw[6].y, &tw[6].x);
}

// DIT, bit-reversed input in X (element brev7(r*32+lane)), natural output.
__device__ __forceinline__ void fft128_warp(float2 X[4], const float2 tw[7],
                                            int lane, float sign) {
    #pragma unroll
    for (int s = 0; s < 5; s++) {       // cross-lane stages len=1..16
        int len = 1<<s;
        float2 w = tw[s];
        #pragma unroll
        for (int r = 0; r < 4; r++) {
            float2 x = X[r];
            float2 o;
            o.x = __shfl_xor_sync(0xffffffffu, x.x, len);
            o.y = __shfl_xor_sync(0xffffffffu, x.y, len);
            if ((lane & len) == 0) X[r] = cadd(x, cmul(w, o));
            else                   X[r] = csub(o, cmul(w, x));
        }
    }
    {   // len=32: pairs (X0,X1),(X2,X3), j=lane
        float2 w = tw[5];
        float2 t = cmul(w, X[1]);
        float2 a = cadd(X[0], t), b = csub(X[0], t); X[0]=a; X[1]=b;
        t = cmul(w, X[3]);
        a = cadd(X[2], t); b = csub(X[2], t); X[2]=a; X[3]=b;
    }
    {   // len=64: (X0,X2) j=lane; (X1,X3) j=lane+32 -> w2 = sign*i*w
        float2 w = tw[6];
        float2 w2 = make_float2(-sign*w.y, sign*w.x);
        float2 t = cmul(w, X[2]);
        float2 a0 = cadd(X[0], t), a2 = csub(X[0], t);
        t = cmul(w2, X[3]);
        float2 a1 = cadd(X[1], t), a3 = csub(X[1], t);
        X[0]=a0; X[1]=a1; X[2]=a2; X[3]=a3;
    }
}

// gather bit-reversed elements of row w: idx(r) = 4*brev5(lane) + c(r)
#define FFT_GATHER(X, SH, w, lane) do {                          \
    int _q4 = 4*(int)(__brev((unsigned)(lane))>>27);             \
    X[0]=SH[w][SWZ(_q4+0)]; X[1]=SH[w][SWZ(_q4+2)];              \
    X[2]=SH[w][SWZ(_q4+1)]; X[3]=SH[w][SWZ(_q4+3)];              \
} while(0)

// ---- z-axis r2c: read ras (c,a0,a1,z), write spec (c,k,a1,a0), k<65 ------
// line l = a1*128 + a0 (a0 fast); 16 lines/block, 512 thr = 16 warps.
__global__ void __launch_bounds__(512) fft_r2c_z() {
    __shared__ float2 sh[16][129];
    const float* s = g_ras  + (size_t)blockIdx.y*VOL;
    float2*      d = g_spec + (size_t)blockIdx.y*CH_SPEC;
    int l0 = blockIdx.x*16, tid = threadIdx.x;
    for (int item = tid; item < 16*128; item += 512) {
        int ll = item>>7, z = item&127;
        int l = l0+ll;
        sh[ll][SWZ(z)] = make_float2(s[((l&127)*128 + (l>>7))*128 + z], 0.f);
    }
    __syncthreads();
    int w = tid>>5, lane = tid&31;
    float2 tw[7]; make_tw(tw, lane, -1.f);
    float2 X[4];
    FFT_GATHER(X, sh, w, lane);
    fft128_warp(X, tw, lane, -1.f);
    #pragma unroll
    for (int r = 0; r < 4; r++) sh[w][SWZ(r*32+lane)] = X[r];
    __syncthreads();
    for (int item = tid; item < 16*KH; item += 512) {
        int k = item>>4, ll = item&15;
        int l = l0+ll;
        d[k*16384 + (l>>7)*128 + (l&127)] = sh[ll][SWZ(k)];
    }
}

// ---- y-axis c2c (in place), spec (c,k,a1,a0): line l = k*128 + a0 --------
__global__ void __launch_bounds__(512) fft_c2c_y(float sign) {
    __shared__ float2 sh[16][129];
    float2* d = g_spec + (size_t)blockIdx.y*CH_SPEC;
    int l0 = blockIdx.x*16, tid = threadIdx.x;
    for (int item = tid; item < 16*128; item += 512) {
        int j = item>>4, ll = item&15;
        int l = l0+ll;
        sh[ll][SWZ(j)] = d[(l>>7)*16384 + j*128 + (l&127)];
    }
    __syncthreads();
    int w = tid>>5, lane = tid&31;
    float2 tw[7]; make_tw(tw, lane, sign);
    float2 X[4];
    FFT_GATHER(X, sh, w, lane);
    fft128_warp(X, tw, lane, sign);
    #pragma unroll
    for (int r = 0; r < 4; r++) sh[w][SWZ(r*32+lane)] = X[r];
    __syncthreads();
    for (int item = tid; item < 16*128; item += 512) {
        int j = item>>4, ll = item&15;
        int l = l0+ll;
        d[(l>>7)*16384 + j*128 + (l&127)] = sh[ll][SWZ(j)];
    }
}

// ---- fused x-axis: fwd FFT (3ch) + combine + inverse FFT, all in regs ----
// line l = k*128 + jj (jj=a1); elements along a0 (contiguous). 8 lines/block.
// meshgrid 'xy' quirk: ch0 multiplier uses a1 (jj), ch1 uses a0 (e).
__global__ void __launch_bounds__(256) fft_x_fused() {
    __shared__ float2 sh[3][8][129];
    int l0 = blockIdx.x*8, tid = threadIdx.x;
    #pragma unroll
    for (int c = 0; c < 3; c++)
        for (int item = tid; item < 8*128; item += 256) {
            int ll = item>>7, i = item&127;
            sh[c][ll][SWZ(i)] = g_spec[(size_t)c*CH_SPEC + (size_t)(l0+ll)*128 + i];
        }
    __syncthreads();
    int w = tid>>5, lane = tid&31;
    float2 tw[7]; make_tw(tw, lane, -1.f);
    float2 A[3][4];
    #pragma unroll
    for (int c = 0; c < 3; c++) {
        FFT_GATHER(A[c], sh[c], w, lane);
        fft128_warp(A[c], tw, lane, -1.f);
    }
    // pointwise combine into A[0]
    int l = l0 + w;
    int k = l>>7, jj = l&127;
    const float wv = 2.f*CUDART_PI_F/128.f;
    float s_j,c_j,s_k,c_k;
    __sincosf(wv*(float)jj, &s_j, &c_j);
    __sincosf(wv*(float)k,  &s_k, &c_k);
    float m0 = 128.f*s_j, m2 = 128.f*s_k;
    #pragma unroll
    for (int r = 0; r < 4; r++) {
        int e = r*32 + lane;
        float s_i,c_i; __sincosf(wv*(float)e, &s_i, &c_i);
        float m1 = 128.f*s_i;
        float lap = 32768.f*((c_j-1.f)+(c_i-1.f)+(c_k-1.f));
        float dre = -(m0*A[0][r].y + m1*A[1][r].y + m2*A[2][r].y);
        float dimg =  (m0*A[0][r].x + m1*A[1][r].x + m2*A[2][r].x);
        float inv = 1.f/(lap + 1e-6f);
        A[0][r] = make_float2(dre*inv, dimg*inv);
        if ((k|jj|e) == 0) A[0][r] = make_float2(0.f,0.f);
    }
    // inverse FFT: bounce through own smem row for bit reversal
    #pragma unroll
    for (int r = 0; r < 4; r++) sh[0][w][SWZ(r*32+lane)] = A[0][r];
    __syncwarp();
    #pragma unroll
    for (int s = 0; s < 7; s++) tw[s].y = -tw[s].y;   // conjugate -> inverse
    float2 Xo[4];
    FFT_GATHER(Xo, sh[0], w, lane);
    fft128_warp(Xo, tw, lane, +1.f);
    #pragma unroll
    for (int r = 0; r < 4; r++) sh[0][w][SWZ(r*32+lane)] = Xo[r];
    __syncthreads();
    for (int item = tid; item < 8*128; item += 256) {
        int ll = item>>7, i = item&127;
        g_spec[(size_t)(l0+ll)*128 + i] = sh[0][ll][SWZ(i)];
    }
}

// ---- z-axis c2r: stage half-spectrum + Hermitian mirror, inv FFT, write --
// line l = a1*128 + a0 (a0 fast); out layout (a0, a1, z).
__global__ void __launch_bounds__(512) fft_c2r_z(float* __restrict__ o) {
    __shared__ float2 sh[16][129];
    int l0 = blockIdx.x*16, tid = threadIdx.x;
    for (int item = tid; item < 16*KH; item += 512) {
        int k = item>>4, ll = item&15;
        int l = l0+ll;
        float2 v = g_spec[k*16384 + (l>>7)*128 + (l&127)];
        sh[ll][SWZ(k)] = v;
        if (k >= 1 && k < 64) sh[ll][SWZ(128-k)] = make_float2(v.x, -v.y);
    }
    __syncthreads();
    int w = tid>>5, lane = tid&31;
    float2 tw[7]; make_tw(tw, lane, +1.f);
    float2 X[4];
    FFT_GATHER(X, sh, w, lane);
    fft128_warp(X, tw, lane, +1.f);
    #pragma unroll
    for (int r = 0; r < 4; r++) sh[w][SWZ(r*32+lane)] = X[r];
    __syncthreads();
    const float scale = 1.f/(float)VOL;
    for (int item = tid; item < 16*128; item += 512) {
        int ll = item>>7, z = item&127;
        int l = l0+ll;
        o[((l&127)*128 + (l>>7))*128 + z] = sh[ll][SWZ(z)].x * scale;
    }
}

// ---------------- trilinear gather at points; per-batch sums ----------------
__global__ void interp_kernel(const float* __restrict__ V, const float* __restrict__ phi, int b) {
    int p = blockIdx.x*blockDim.x + threadIdx.x;
    float x0 = V[3*p+0]*128.f, x1 = V[3*p+1]*128.f, x2 = V[3*p+2]*128.f;
    float fl0 = floorf(x0), fl1 = floorf(x1), fl2 = floorf(x2);
    int a0 = ((int)fl0)&127, a1 = ((int)fl1)&127, a2 = ((int)fl2)&127;
    int b0 = ((int)ceilf(x0))&127, b1 = ((int)ceilf(x1))&127, b2 = ((int)ceilf(x2))&127;
    float f0 = x0-fl0, f1 = x1-fl1, f2 = x2-fl2;
    float fv = 0.f;
    #pragma unroll
    for (int c = 0; c < 8; c++) {
        int c0 = (c>>2)&1, c1 = (c>>1)&1, c2 = c&1;
        int i0 = c0 ? b0 : a0;
        int i1 = c1 ? b1 : a1;
        int i2 = c2 ? b2 : a2;
        float w = (c0 ? f0 : 1.f-f0) * (c1 ? f1 : 1.f-f1) * (c2 ? f2 : 1.f-f2);
        fv += w * phi[(i0*128 + i1)*128 + i2];
    }
    #pragma unroll
    for (int o = 16; o; o >>= 1) fv += __shfl_down_sync(0xffffffffu, fv, o);
    if ((threadIdx.x & 31) == 0) atomicAdd(&g_scalar[2*b], fv);
    if (p == 0) g_scalar[2*b+1] = phi[0];
}

// ---------------- final normalize in place ----------------
__global__ void norm_kernel(float* __restrict__ phi, int b) {
    int idx = blockIdx.x*blockDim.x + threadIdx.x;
    float mean = g_scalar[2*b] * (1.f/(float)NPTS);
    float fv0  = g_scalar[2*b+1] - mean;
    float s = -0.5f / fabsf(fv0);
    phi[idx] = (phi[idx] - mean) * s;
}

// ---------------- host ----------------
extern "C" void kernel_launch(void* const* d_in, const int* in_sizes, int n_in,
                              void* d_out, int out_size) {
    (void)in_sizes; (void)n_in; (void)out_size;
    const float* V = (const float*)d_in[0];
    const float* N = (const float*)d_in[1];
    float* out = (float*)d_out;

    for (int b = 0; b < NB; b++) {
        const float* Vb = V + (size_t)b*NPTS*3;
        const float* Nb = N + (size_t)b*NPTS*3;
        float* outb = out + (size_t)b*VOL;

        zero_kernel  <<<3*VOL/4/256, 256>>>(b);
        raster_kernel<<<NPTS/256, 256>>>(Vb, Nb);

        fft_r2c_z  <<<dim3(16384/16, 3), 512>>>();
        fft_c2c_y  <<<dim3(KH*128/16, 3), 512>>>(-1.f);
        fft_x_fused<<<dim3(KH*128/8,  1), 256>>>();
        fft_c2c_y  <<<dim3(KH*128/16, 1), 512>>>(+1.f);
        fft_c2r_z  <<<dim3(16384/16,  1), 512>>>(outb);

        interp_kernel<<<NPTS/256, 256>>>(Vb, outb, b);
        norm_kernel  <<<VOL/256,  256>>>(outb, b);
    }
}

// round 9
// speedup vs baseline: 1.8739x; 1.0846x over previous
#include <cuda_runtime.h>
#include <math_constants.h>
#include <cstdint>

#define VOL (128*128*128)
#define KH 65                         // half-spectrum planes along z (rfft)
#define MLEN (KH*128)                 // 8320 spectral (k,a1) entries per a0
#define NPTS 65536
#define NB 4

#define SWZ(z) ((z) ^ (((z)>>4)&7))

// ---------------- scratch ----------------
__device__ float  g_ras[NB*3*VOL];             // (b,c, a0,a1,z)
__device__ float2 g_spec[(size_t)NB*3*128*MLEN]; // (b,c, a0, m=k*128+a1)
__device__ float  g_scalar[2*NB];

// ---------------- rasterize ----------------
__global__ void raster_kernel(const float* __restrict__ V, const float* __restrict__ N) {
    int b = blockIdx.y;
    int p = blockIdx.x*blockDim.x + threadIdx.x;
    const float* Vb = V + (size_t)b*NPTS*3;
    const float* Nb = N + (size_t)b*NPTS*3;
    float* ras = g_ras + (size_t)b*3*VOL;
    float x0 = Vb[3*p+0]*128.f, x1 = Vb[3*p+1]*128.f, x2 = Vb[3*p+2]*128.f;
    float n0 = Nb[3*p+0], n1 = Nb[3*p+1], n2 = Nb[3*p+2];
    float fl0 = floorf(x0), fl1 = floorf(x1), fl2 = floorf(x2);
    int a0 = ((int)fl0)&127, a1 = ((int)fl1)&127, a2 = ((int)fl2)&127;
    int b0 = ((int)ceilf(x0))&127, b1 = ((int)ceilf(x1))&127, b2 = ((int)ceilf(x2))&127;
    float f0 = x0-fl0, f1 = x1-fl1, f2 = x2-fl2;
    #pragma unroll
    for (int c = 0; c < 8; c++) {
        int c0 = (c>>2)&1, c1 = (c>>1)&1, c2 = c&1;
        int i0 = c0 ? b0 : a0;
        int i1 = c1 ? b1 : a1;
        int i2 = c2 ? b2 : a2;
        float w = (c0 ? f0 : 1.f-f0) * (c1 ? f1 : 1.f-f1) * (c2 ? f2 : 1.f-f2);
        int idx = (i0*128 + i1)*128 + i2;
        atomicAdd(&ras[idx],       w*n0);
        atomicAdd(&ras[VOL+idx],   w*n1);
        atomicAdd(&ras[2*VOL+idx], w*n2);
    }
}

// ---------------- register-resident 128-pt FFT (one warp per line) --------
__device__ __forceinline__ float2 cadd(float2 a, float2 b){return make_float2(a.x+b.x, a.y+b.y);}
__device__ __forceinline__ float2 csub(float2 a, float2 b){return make_float2(a.x-b.x, a.y-b.y);}
__device__ __forceinline__ float2 cmul(float2 a, float2 b){return make_float2(a.x*b.x-a.y*b.y, a.x*b.y+a.y*b.x);}

__device__ __forceinline__ void make_tw(float2 tw[7], int lane, float sign) {
    tw[0] = make_float2(1.f, 0.f);
    #pragma unroll
    for (int s = 1; s <= 4; s++) {
        int len = 1<<s;
        float ang = sign*CUDART_PI_F*(float)(lane&(len-1))/(float)len;
        __sincosf(ang, &tw[s].y, &tw[s].x);
    }
    float ang = sign*CUDART_PI_F*(float)lane/32.f;
    __sincosf(ang, &tw[5].y, &tw[5].x);
    ang = sign*CUDART_PI_F*(float)lane/64.f;
    __sincosf(ang, &tw[6].y, &tw[6].x);
}

// DIT, bit-reversed input (element brev7(r*32+lane)), natural order output k=r*32+lane.
__device__ __forceinline__ void fft128_warp(float2 X[4], const float2 tw[7],
                                            int lane, float sign) {
    #pragma unroll
    for (int s = 0; s < 5; s++) {
        int len = 1<<s;
        float2 w = tw[s];
        #pragma unroll
        for (int r = 0; r < 4; r++) {
            float2 x = X[r];
            float2 o;
            o.x = __shfl_xor_sync(0xffffffffu, x.x, len);
            o.y = __shfl_xor_sync(0xffffffffu, x.y, len);
            if ((lane & len) == 0) X[r] = cadd(x, cmul(w, o));
            else                   X[r] = csub(o, cmul(w, x));
        }
    }
    {
        float2 w = tw[5];
        float2 t = cmul(w, X[1]);
        float2 a = cadd(X[0], t), b = csub(X[0], t); X[0]=a; X[1]=b;
        t = cmul(w, X[3]);
        a = cadd(X[2], t); b = csub(X[2], t); X[2]=a; X[3]=b;
    }
    {
        float2 w = tw[6];
        float2 w2 = make_float2(-sign*w.y, sign*w.x);
        float2 t = cmul(w, X[2]);
        float2 a0 = cadd(X[0], t), a2 = csub(X[0], t);
        t = cmul(w2, X[3]);
        float2 a1 = cadd(X[1], t), a3 = csub(X[1], t);
        X[0]=a0; X[1]=a1; X[2]=a2; X[3]=a3;
    }
}

// ---- PassA: fused z-r2c + y-fwd per (b,c,a0) plane -----------------------
// smem plane sh[k<65][SWZ(a1)], row width 129. Writes spec (b,c,a0,m).
__global__ void __launch_bounds__(512) passA() {
    extern __shared__ float2 sh[];          // 65*129 float2
    int a0 = blockIdx.x, c = blockIdx.y, b = blockIdx.z;
    const float* src = g_ras + ((size_t)(b*3+c)*128 + a0)*16384;
    float2* dspec = g_spec + ((size_t)(b*3+c)*128 + a0)*MLEN;
    int w = threadIdx.x>>5, lane = threadIdx.x&31;
    int q4 = 4*(int)(__brev((unsigned)lane)>>27);
    float2 tw[7]; make_tw(tw, lane, -1.f);
    // z-phase: 8 lines per warp, bit-reversed direct loads
    for (int a1 = w; a1 < 128; a1 += 16) {
        const float* ln = src + a1*128;
        float2 X[4];
        X[0] = make_float2(ln[q4+0], 0.f);
        X[1] = make_float2(ln[q4+2], 0.f);
        X[2] = make_float2(ln[q4+1], 0.f);
        X[3] = make_float2(ln[q4+3], 0.f);
        fft128_warp(X, tw, lane, -1.f);
        int p = SWZ(a1);
        sh[lane*129 + p]      = X[0];           // k = lane
        sh[(32+lane)*129 + p] = X[1];           // k = 32+lane
        if (lane == 0) sh[64*129 + p] = X[2];   // k = 64
    }
    __syncthreads();
    // y-phase: 65 lines, write registers -> global coalesced
    for (int k = w; k < 65; k += 16) {
        float2* row = sh + k*129;
        float2 X[4];
        X[0]=row[SWZ(q4+0)]; X[1]=row[SWZ(q4+2)];
        X[2]=row[SWZ(q4+1)]; X[3]=row[SWZ(q4+3)];
        fft128_warp(X, tw, lane, -1.f);
        float2* dst = dspec + k*128;
        dst[lane]    = X[0];
        dst[32+lane] = X[1];
        dst[64+lane] = X[2];
        dst[96+lane] = X[3];
    }
}

// ---- PassB: fused x-fwd(3ch) + spectral combine + x-inv (ch0) ------------
// lines = fixed m (8 per block), elements a0 strided by MLEN.
// meshgrid 'xy' quirk: ch0 multiplier uses a1(jj), ch1 uses a0(e).
__global__ void __launch_bounds__(256) passB() {
    __shared__ float2 sh[3][8][129];
    int m0 = blockIdx.x*8, b = blockIdx.y, tid = threadIdx.x;
    size_t base = (size_t)(b*3)*128*MLEN;
    #pragma unroll
    for (int c = 0; c < 3; c++)
        for (int item = tid; item < 1024; item += 256) {
            int a0 = item>>3, mm = item&7;
            sh[c][mm][SWZ(a0)] = g_spec[base + (size_t)c*128*MLEN + (size_t)a0*MLEN + m0 + mm];
        }
    __syncthreads();
    int w = tid>>5, lane = tid&31;
    int q4 = 4*(int)(__brev((unsigned)lane)>>27);
    float2 tw[7]; make_tw(tw, lane, -1.f);
    float2 A[3][4];
    #pragma unroll
    for (int c = 0; c < 3; c++) {
        A[c][0]=sh[c][w][SWZ(q4+0)]; A[c][1]=sh[c][w][SWZ(q4+2)];
        A[c][2]=sh[c][w][SWZ(q4+1)]; A[c][3]=sh[c][w][SWZ(q4+3)];
        fft128_warp(A[c], tw, lane, -1.f);
    }
    int m = m0 + w;
    int k = m>>7, jj = m&127;
    const float wv = 2.f*CUDART_PI_F/128.f;
    float s_j,c_j,s_k,c_k;
    __sincosf(wv*(float)jj, &s_j, &c_j);
    __sincosf(wv*(float)k,  &s_k, &c_k);
    float m0m = 128.f*s_j, m2m = 128.f*s_k;
    #pragma unroll
    for (int r = 0; r < 4; r++) {
        int e = r*32 + lane;
        float s_i,c_i; __sincosf(wv*(float)e, &s_i, &c_i);
        float m1m = 128.f*s_i;
        float lap = 32768.f*((c_j-1.f)+(c_i-1.f)+(c_k-1.f));
        float dre = -(m0m*A[0][r].y + m1m*A[1][r].y + m2m*A[2][r].y);
        float dimg =  (m0m*A[0][r].x + m1m*A[1][r].x + m2m*A[2][r].x);
        float inv = 1.f/(lap + 1e-6f);
        A[0][r] = make_float2(dre*inv, dimg*inv);
        if ((k|jj|e) == 0) A[0][r] = make_float2(0.f,0.f);
    }
    #pragma unroll
    for (int r = 0; r < 4; r++) sh[0][w][SWZ(r*32+lane)] = A[0][r];
    __syncwarp();
    #pragma unroll
    for (int s = 0; s < 7; s++) tw[s].y = -tw[s].y;   // conjugate -> inverse
    float2 Xo[4];
    Xo[0]=sh[0][w][SWZ(q4+0)]; Xo[1]=sh[0][w][SWZ(q4+2)];
    Xo[2]=sh[0][w][SWZ(q4+1)]; Xo[3]=sh[0][w][SWZ(q4+3)];
    fft128_warp(Xo, tw, lane, +1.f);
    #pragma unroll
    for (int r = 0; r < 4; r++) sh[0][w][SWZ(r*32+lane)] = Xo[r];
    __syncthreads();
    for (int item = tid; item < 1024; item += 256) {
        int a0 = item>>3, mm = item&7;
        g_spec[base + (size_t)a0*MLEN + m0 + mm] = sh[0][mm][SWZ(a0)];
    }
}

// ---- PassC: fused y-inv + z-c2r per (b,a0) plane -------------------------
__global__ void __launch_bounds__(512) passC(float* __restrict__ out) {
    extern __shared__ float2 sh[];          // 65*129 float2
    int a0 = blockIdx.x, b = blockIdx.y;
    const float2* sspec = g_spec + ((size_t)(b*3)*128 + a0)*MLEN;
    float* o = out + ((size_t)b*128 + a0)*16384;
    int tid = threadIdx.x, w = tid>>5, lane = tid&31;
    for (int item = tid; item < MLEN; item += 512) {
        int k = item>>7, a1 = item&127;
        sh[k*129 + SWZ(a1)] = sspec[item];
    }
    __syncthreads();
    int q4 = 4*(int)(__brev((unsigned)lane)>>27);
    float2 tw[7]; make_tw(tw, lane, +1.f);
    // y-inverse: 65 lines, in-place per row
    for (int k = w; k < 65; k += 16) {
        float2* row = sh + k*129;
        float2 X[4];
        X[0]=row[SWZ(q4+0)]; X[1]=row[SWZ(q4+2)];
        X[2]=row[SWZ(q4+1)]; X[3]=row[SWZ(q4+3)];
        fft128_warp(X, tw, lane, +1.f);
        row[SWZ(lane)]    = X[0];
        row[SWZ(32+lane)] = X[1];
        row[SWZ(64+lane)] = X[2];
        row[SWZ(96+lane)] = X[3];
    }
    __syncthreads();
    // c2r along z(k): Hermitian mirror in the gather, direct global write
    const float scale = 1.f/(float)VOL;
    for (int a1 = w; a1 < 128; a1 += 16) {
        int p = SWZ(a1);
        float2 X[4];
        #pragma unroll
        for (int r = 0; r < 4; r++) {
            int n = q4 + ((r==0)?0:(r==1)?2:(r==2)?1:3);
            float2 v = (n <= 64) ? sh[n*129+p] : sh[(128-n)*129+p];
            if (n > 64) v.y = -v.y;
            X[r] = v;
        }
        fft128_warp(X, tw, lane, +1.f);
        float* oz = o + a1*128;
        oz[lane]    = X[0].x*scale;
        oz[32+lane] = X[1].x*scale;
        oz[64+lane] = X[2].x*scale;
        oz[96+lane] = X[3].x*scale;
    }
}

// ---------------- trilinear gather at points; per-batch sums ----------------
__global__ void interp_kernel(const float* __restrict__ V, const float* __restrict__ out) {
    int b = blockIdx.y;
    int p = blockIdx.x*blockDim.x + threadIdx.x;
    const float* Vb  = V + (size_t)b*NPTS*3;
    const float* phi = out + (size_t)b*VOL;
    float x0 = Vb[3*p+0]*128.f, x1 = Vb[3*p+1]*128.f, x2 = Vb[3*p+2]*128.f;
    float fl0 = floorf(x0), fl1 = floorf(x1), fl2 = floorf(x2);
    int a0 = ((int)fl0)&127, a1 = ((int)fl1)&127, a2 = ((int)fl2)&127;
    int b0 = ((int)ceilf(x0))&127, b1 = ((int)ceilf(x1))&127, b2 = ((int)ceilf(x2))&127;
    float f0 = x0-fl0, f1 = x1-fl1, f2 = x2-fl2;
    float fv = 0.f;
    #pragma unroll
    for (int c = 0; c < 8; c++) {
        int c0 = (c>>2)&1, c1 = (c>>1)&1, c2 = c&1;
        int i0 = c0 ? b0 : a0;
        int i1 = c1 ? b1 : a1;
        int i2 = c2 ? b2 : a2;
        float w = (c0 ? f0 : 1.f-f0) * (c1 ? f1 : 1.f-f1) * (c2 ? f2 : 1.f-f2);
        fv += w * phi[(i0*128 + i1)*128 + i2];
    }
    #pragma unroll
    for (int o = 16; o; o >>= 1) fv += __shfl_down_sync(0xffffffffu, fv, o);
    if ((threadIdx.x & 31) == 0) atomicAdd(&g_scalar[2*b], fv);
    if (p == 0) g_scalar[2*b+1] = phi[0];
}

// ---------------- final normalize in place ----------------
__global__ void norm_kernel(float* __restrict__ out) {
    int b = blockIdx.y;
    int idx = blockIdx.x*blockDim.x + threadIdx.x;
    float* phi = out + (size_t)b*VOL;
    float mean = g_scalar[2*b] * (1.f/(float)NPTS);
    float fv0  = g_scalar[2*b+1] - mean;
    float s = -0.5f / fabsf(fv0);
    phi[idx] = (phi[idx] - mean) * s;
}

// ---------------- host ----------------
extern "C" void kernel_launch(void* const* d_in, const int* in_sizes, int n_in,
                              void* d_out, int out_size) {
    (void)in_sizes; (void)n_in; (void)out_size;
    const float* V = (const float*)d_in[0];
    const float* N = (const float*)d_in[1];
    float* out = (float*)d_out;

    const int PLANE_SMEM = 65*129*sizeof(float2);   // 67,080 B
    cudaFuncSetAttribute(passA, cudaFuncAttributeMaxDynamicSharedMemorySize, PLANE_SMEM);
    cudaFuncSetAttribute(passC, cudaFuncAttributeMaxDynamicSharedMemorySize, PLANE_SMEM);

    void *ras_pv, *sc_pv;
    cudaGetSymbolAddress(&ras_pv, g_ras);
    cudaGetSymbolAddress(&sc_pv,  g_scalar);
    cudaMemsetAsync(ras_pv, 0, (size_t)NB*3*VOL*sizeof(float));
    cudaMemsetAsync(sc_pv,  0, 2*NB*sizeof(float));

    raster_kernel<<<dim3(NPTS/256, NB), 256>>>(V, N);
    passA<<<dim3(128, 3, NB), 512, PLANE_SMEM>>>();
    passB<<<dim3(MLEN/8, NB), 256>>>();
    passC<<<dim3(128, NB), 512, PLANE_SMEM>>>(out);
    interp_kernel<<<dim3(NPTS/256, NB), 256>>>(V, out);
    norm_kernel<<<dim3(VOL/256, NB), 256>>>(out);
}

// round 10
// speedup vs baseline: 1.9389x; 1.0346x over previous
#include <cuda_runtime.h>
#include <math_constants.h>
#include <cstdint>

#define VOL (128*128*128)
#define KH 65                         // half-spectrum planes along z (rfft)
#define MLEN (KH*128)                 // 8320 spectral (k,a1) entries per a0
#define NPTS 65536
#define NB 4

#define SWZ(z) ((z) ^ (((z)>>4)&7))

// ---------------- scratch ----------------
__device__ float  g_ras[NB*3*VOL];             // (b,c, a0,a1,z)
__device__ float2 g_spec[(size_t)NB*3*128*MLEN]; // (b,c, a0, m=k*128+a1)
__device__ float  g_scalar[2*NB];

// ---------------- rasterize ----------------
__global__ void raster_kernel(const float* __restrict__ V, const float* __restrict__ N) {
    int b = blockIdx.y;
    int p = blockIdx.x*blockDim.x + threadIdx.x;
    const float* Vb = V + (size_t)b*NPTS*3;
    const float* Nb = N + (size_t)b*NPTS*3;
    float* ras = g_ras + (size_t)b*3*VOL;
    float x0 = Vb[3*p+0]*128.f, x1 = Vb[3*p+1]*128.f, x2 = Vb[3*p+2]*128.f;
    float n0 = Nb[3*p+0], n1 = Nb[3*p+1], n2 = Nb[3*p+2];
    float fl0 = floorf(x0), fl1 = floorf(x1), fl2 = floorf(x2);
    int a0 = ((int)fl0)&127, a1 = ((int)fl1)&127, a2 = ((int)fl2)&127;
    int b0 = ((int)ceilf(x0))&127, b1 = ((int)ceilf(x1))&127, b2 = ((int)ceilf(x2))&127;
    float f0 = x0-fl0, f1 = x1-fl1, f2 = x2-fl2;
    #pragma unroll
    for (int c = 0; c < 8; c++) {
        int c0 = (c>>2)&1, c1 = (c>>1)&1, c2 = c&1;
        int i0 = c0 ? b0 : a0;
        int i1 = c1 ? b1 : a1;
        int i2 = c2 ? b2 : a2;
        float w = (c0 ? f0 : 1.f-f0) * (c1 ? f1 : 1.f-f1) * (c2 ? f2 : 1.f-f2);
        int idx = (i0*128 + i1)*128 + i2;
        atomicAdd(&ras[idx],       w*n0);
        atomicAdd(&ras[VOL+idx],   w*n1);
        atomicAdd(&ras[2*VOL+idx], w*n2);
    }
}

// ---------------- register-resident 128-pt FFT (one warp per line) --------
__device__ __forceinline__ float2 cadd(float2 a, float2 b){return make_float2(a.x+b.x, a.y+b.y);}
__device__ __forceinline__ float2 csub(float2 a, float2 b){return make_float2(a.x-b.x, a.y-b.y);}
__device__ __forceinline__ float2 cmul(float2 a, float2 b){return make_float2(a.x*b.x-a.y*b.y, a.x*b.y+a.y*b.x);}

__device__ __forceinline__ void make_tw(float2 tw[7], int lane, float sign) {
    tw[0] = make_float2(1.f, 0.f);
    #pragma unroll
    for (int s = 1; s <= 4; s++) {
        int len = 1<<s;
        float ang = sign*CUDART_PI_F*(float)(lane&(len-1))/(float)len;
        __sincosf(ang, &tw[s].y, &tw[s].x);
    }
    float ang = sign*CUDART_PI_F*(float)lane/32.f;
    __sincosf(ang, &tw[5].y, &tw[5].x);
    ang = sign*CUDART_PI_F*(float)lane/64.f;
    __sincosf(ang, &tw[6].y, &tw[6].x);
}

// DIT, bit-reversed input (element brev7(r*32+lane)), natural order output k=r*32+lane.
__device__ __forceinline__ void fft128_warp(float2 X[4], const float2 tw[7],
                                            int lane, float sign) {
    #pragma unroll
    for (int s = 0; s < 5; s++) {
        int len = 1<<s;
        float2 w = tw[s];
        #pragma unroll
        for (int r = 0; r < 4; r++) {
            float2 x = X[r];
            float2 o;
            o.x = __shfl_xor_sync(0xffffffffu, x.x, len);
            o.y = __shfl_xor_sync(0xffffffffu, x.y, len);
            if ((lane & len) == 0) X[r] = cadd(x, cmul(w, o));
            else                   X[r] = csub(o, cmul(w, x));
        }
    }
    {
        float2 w = tw[5];
        float2 t = cmul(w, X[1]);
        float2 a = cadd(X[0], t), b = csub(X[0], t); X[0]=a; X[1]=b;
        t = cmul(w, X[3]);
        a = cadd(X[2], t); b = csub(X[2], t); X[2]=a; X[3]=b;
    }
    {
        float2 w = tw[6];
        float2 w2 = make_float2(-sign*w.y, sign*w.x);
        float2 t = cmul(w, X[2]);
        float2 a0 = cadd(X[0], t), a2 = csub(X[0], t);
        t = cmul(w2, X[3]);
        float2 a1 = cadd(X[1], t), a3 = csub(X[1], t);
        X[0]=a0; X[1]=a1; X[2]=a2; X[3]=a3;
    }
}

// ---- PassA: fused z-r2c + y-fwd per (b,c,a0) plane -----------------------
__global__ void __launch_bounds__(512) passA() {
    extern __shared__ float2 sh[];          // 65*129 float2
    int a0 = blockIdx.x, c = blockIdx.y, b = blockIdx.z;
    const float* src = g_ras + ((size_t)(b*3+c)*128 + a0)*16384;
    float2* dspec = g_spec + ((size_t)(b*3+c)*128 + a0)*MLEN;
    int w = threadIdx.x>>5, lane = threadIdx.x&31;
    int q4 = 4*(int)(__brev((unsigned)lane)>>27);
    float2 tw[7]; make_tw(tw, lane, -1.f);
    // z-phase: 8 lines per warp, bit-reversed direct loads
    for (int a1 = w; a1 < 128; a1 += 16) {
        const float* ln = src + a1*128;
        float2 X[4];
        X[0] = make_float2(ln[q4+0], 0.f);
        X[1] = make_float2(ln[q4+2], 0.f);
        X[2] = make_float2(ln[q4+1], 0.f);
        X[3] = make_float2(ln[q4+3], 0.f);
        fft128_warp(X, tw, lane, -1.f);
        int p = SWZ(a1);
        sh[lane*129 + p]      = X[0];           // k = lane
        sh[(32+lane)*129 + p] = X[1];           // k = 32+lane
        if (lane == 0) sh[64*129 + p] = X[2];   // k = 64
    }
    __syncthreads();
    // y-phase: 65 lines, write registers -> global coalesced
    for (int k = w; k < 65; k += 16) {
        float2* row = sh + k*129;
        float2 X[4];
        X[0]=row[SWZ(q4+0)]; X[1]=row[SWZ(q4+2)];
        X[2]=row[SWZ(q4+1)]; X[3]=row[SWZ(q4+3)];
        fft128_warp(X, tw, lane, -1.f);
        float2* dst = dspec + k*128;
        dst[lane]    = X[0];
        dst[32+lane] = X[1];
        dst[64+lane] = X[2];
        dst[96+lane] = X[3];
    }
}

// ---- PassB: fused x-fwd(3ch) + spectral combine + x-inv (ch0) ------------
// meshgrid 'xy' quirk: ch0 multiplier uses a1(jj), ch1 uses a0(e).
__global__ void __launch_bounds__(256) passB() {
    __shared__ float2 sh[3][8][129];
    int m0 = blockIdx.x*8, b = blockIdx.y, tid = threadIdx.x;
    size_t base = (size_t)(b*3)*128*MLEN;
    #pragma unroll
    for (int c = 0; c < 3; c++)
        for (int item = tid; item < 1024; item += 256) {
            int a0 = item>>3, mm = item&7;
            sh[c][mm][SWZ(a0)] = g_spec[base + (size_t)c*128*MLEN + (size_t)a0*MLEN + m0 + mm];
        }
    __syncthreads();
    int w = tid>>5, lane = tid&31;
    int q4 = 4*(int)(__brev((unsigned)lane)>>27);
    float2 tw[7]; make_tw(tw, lane, -1.f);
    float2 A[3][4];
    #pragma unroll
    for (int c = 0; c < 3; c++) {
        A[c][0]=sh[c][w][SWZ(q4+0)]; A[c][1]=sh[c][w][SWZ(q4+2)];
        A[c][2]=sh[c][w][SWZ(q4+1)]; A[c][3]=sh[c][w][SWZ(q4+3)];
        fft128_warp(A[c], tw, lane, -1.f);
    }
    int m = m0 + w;
    int k = m>>7, jj = m&127;
    const float wv = 2.f*CUDART_PI_F/128.f;
    float s_j,c_j,s_k,c_k;
    __sincosf(wv*(float)jj, &s_j, &c_j);
    __sincosf(wv*(float)k,  &s_k, &c_k);
    float m0m = 128.f*s_j, m2m = 128.f*s_k;
    #pragma unroll
    for (int r = 0; r < 4; r++) {
        int e = r*32 + lane;
        float s_i,c_i; __sincosf(wv*(float)e, &s_i, &c_i);
        float m1m = 128.f*s_i;
        float lap = 32768.f*((c_j-1.f)+(c_i-1.f)+(c_k-1.f));
        float dre = -(m0m*A[0][r].y + m1m*A[1][r].y + m2m*A[2][r].y);
        float dimg =  (m0m*A[0][r].x + m1m*A[1][r].x + m2m*A[2][r].x);
        float inv = 1.f/(lap + 1e-6f);
        A[0][r] = make_float2(dre*inv, dimg*inv);
        if ((k|jj|e) == 0) A[0][r] = make_float2(0.f,0.f);
    }
    #pragma unroll
    for (int r = 0; r < 4; r++) sh[0][w][SWZ(r*32+lane)] = A[0][r];
    __syncwarp();
    #pragma unroll
    for (int s = 0; s < 7; s++) tw[s].y = -tw[s].y;   // conjugate -> inverse
    float2 Xo[4];
    Xo[0]=sh[0][w][SWZ(q4+0)]; Xo[1]=sh[0][w][SWZ(q4+2)];
    Xo[2]=sh[0][w][SWZ(q4+1)]; Xo[3]=sh[0][w][SWZ(q4+3)];
    fft128_warp(Xo, tw, lane, +1.f);
    #pragma unroll
    for (int r = 0; r < 4; r++) sh[0][w][SWZ(r*32+lane)] = Xo[r];
    __syncthreads();
    for (int item = tid; item < 1024; item += 256) {
        int a0 = item>>3, mm = item&7;
        g_spec[base + (size_t)a0*MLEN + m0 + mm] = sh[0][mm][SWZ(a0)];
    }
}

// ---- passC1: y-inverse, in place, ch0. One warp per contiguous a1-line ---
// lines enumerated l = a0*65 + k. No __syncthreads (warp-private smem rows).
__global__ void __launch_bounds__(512) passC1() {
    __shared__ float2 sh[16][129];
    int b = blockIdx.y;
    int tid = threadIdx.x, w = tid>>5, lane = tid&31;
    int l = blockIdx.x*16 + w;          // < 8320
    int a0 = l/65, k = l - a0*65;
    float2* ln = g_spec + ((size_t)(b*3)*128 + a0)*MLEN + k*128;
    int q4 = 4*(int)(__brev((unsigned)lane)>>27);
    float2 tw[7]; make_tw(tw, lane, +1.f);
    #pragma unroll
    for (int r = 0; r < 4; r++) sh[w][SWZ(r*32+lane)] = ln[r*32+lane];
    __syncwarp();
    float2 X[4];
    X[0]=sh[w][SWZ(q4+0)]; X[1]=sh[w][SWZ(q4+2)];
    X[2]=sh[w][SWZ(q4+1)]; X[3]=sh[w][SWZ(q4+3)];
    fft128_warp(X, tw, lane, +1.f);
    #pragma unroll
    for (int r = 0; r < 4; r++) ln[r*32+lane] = X[r];
}

// ---- passC2: z-c2r. 16 z-lines/block (consecutive a1, fixed a0) ----------
// stage k<=64 rows + Hermitian mirror, warp w transforms a1-col w.
__global__ void __launch_bounds__(512) passC2(float* __restrict__ out) {
    __shared__ float2 sh[16][129];       // [a1-col][SWZ(k-element)]
    int b = blockIdx.y;
    int a0 = blockIdx.x >> 3, t = blockIdx.x & 7;
    int a1base = t*16;
    const float2* sp = g_spec + ((size_t)(b*3)*128 + a0)*MLEN + a1base;
    float* o = out + ((size_t)b*128 + a0)*16384;
    int tid = threadIdx.x, w = tid>>5, lane = tid&31;
    for (int item = tid; item < 65*16; item += 512) {
        int k = item>>4, col = item&15;
        float2 v = sp[k*128 + col];
        sh[col][SWZ(k)] = v;
        if (k >= 1 && k < 64) sh[col][SWZ(128-k)] = make_float2(v.x, -v.y);
    }
    __syncthreads();
    int q4 = 4*(int)(__brev((unsigned)lane)>>27);
    float2 tw[7]; make_tw(tw, lane, +1.f);
    float2 X[4];
    X[0]=sh[w][SWZ(q4+0)]; X[1]=sh[w][SWZ(q4+2)];
    X[2]=sh[w][SWZ(q4+1)]; X[3]=sh[w][SWZ(q4+3)];
    fft128_warp(X, tw, lane, +1.f);
    const float scale = 1.f/(float)VOL;
    float* oz = o + (a1base + w)*128;
    oz[lane]    = X[0].x*scale;
    oz[32+lane] = X[1].x*scale;
    oz[64+lane] = X[2].x*scale;
    oz[96+lane] = X[3].x*scale;
}

// ---------------- trilinear gather at points; per-batch sums ----------------
__global__ void interp_kernel(const float* __restrict__ V, const float* __restrict__ out) {
    int b = blockIdx.y;
    int p = blockIdx.x*blockDim.x + threadIdx.x;
    const float* Vb  = V + (size_t)b*NPTS*3;
    const float* phi = out + (size_t)b*VOL;
    float x0 = Vb[3*p+0]*128.f, x1 = Vb[3*p+1]*128.f, x2 = Vb[3*p+2]*128.f;
    float fl0 = floorf(x0), fl1 = floorf(x1), fl2 = floorf(x2);
    int a0 = ((int)fl0)&127, a1 = ((int)fl1)&127, a2 = ((int)fl2)&127;
    int b0 = ((int)ceilf(x0))&127, b1 = ((int)ceilf(x1))&127, b2 = ((int)ceilf(x2))&127;
    float f0 = x0-fl0, f1 = x1-fl1, f2 = x2-fl2;
    float fv = 0.f;
    #pragma unroll
    for (int c = 0; c < 8; c++) {
        int c0 = (c>>2)&1, c1 = (c>>1)&1, c2 = c&1;
        int i0 = c0 ? b0 : a0;
        int i1 = c1 ? b1 : a1;
        int i2 = c2 ? b2 : a2;
        float w = (c0 ? f0 : 1.f-f0) * (c1 ? f1 : 1.f-f1) * (c2 ? f2 : 1.f-f2);
        fv += w * phi[(i0*128 + i1)*128 + i2];
    }
    #pragma unroll
    for (int o = 16; o; o >>= 1) fv += __shfl_down_sync(0xffffffffu, fv, o);
    if ((threadIdx.x & 31) == 0) atomicAdd(&g_scalar[2*b], fv);
    if (p == 0) g_scalar[2*b+1] = phi[0];
}

// ---------------- final normalize in place ----------------
__global__ void norm_kernel(float* __restrict__ out) {
    int b = blockIdx.y;
    int idx = blockIdx.x*blockDim.x + threadIdx.x;
    float* phi = out + (size_t)b*VOL;
    float mean = g_scalar[2*b] * (1.f/(float)NPTS);
    float fv0  = g_scalar[2*b+1] - mean;
    float s = -0.5f / fabsf(fv0);
    phi[idx] = (phi[idx] - mean) * s;
}

// ---------------- host ----------------
extern "C" void kernel_launch(void* const* d_in, const int* in_sizes, int n_in,
                              void* d_out, int out_size) {
    (void)in_sizes; (void)n_in; (void)out_size;
    const float* V = (const float*)d_in[0];
    const float* N = (const float*)d_in[1];
    float* out = (float*)d_out;

    const int PLANE_SMEM = 65*129*sizeof(float2);   // 67,080 B
    cudaFuncSetAttribute(passA, cudaFuncAttributeMaxDynamicSharedMemorySize, PLANE_SMEM);

    void *ras_pv, *sc_pv;
    cudaGetSymbolAddress(&ras_pv, g_ras);
    cudaGetSymbolAddress(&sc_pv,  g_scalar);
    cudaMemsetAsync(ras_pv, 0, (size_t)NB*3*VOL*sizeof(float));
    cudaMemsetAsync(sc_pv,  0, 2*NB*sizeof(float));

    raster_kernel<<<dim3(NPTS/256, NB), 256>>>(V, N);
    passA<<<dim3(128, 3, NB), 512, PLANE_SMEM>>>();
    passB<<<dim3(MLEN/8, NB), 256>>>();
    passC1<<<dim3(8320/16, NB), 512>>>();
    passC2<<<dim3(128*8, NB), 512>>>(out);
    interp_kernel<<<dim3(NPTS/256, NB), 256>>>(V, out);
    norm_kernel<<<dim3(VOL/256, NB), 256>>>(out);
}

// round 15
// speedup vs baseline: 2.2129x; 1.1413x over previous
#include <cuda_runtime.h>
#include <math_constants.h>
#include <cstdint>

#define VOL (128*128*128)
#define KH 65                         // half-spectrum planes along z (rfft)
#define MLEN (KH*128)                 // 8320 spectral (k,a1) entries per a0
#define NPTS 65536
#define NB 4

#define SWZ(z) ((z) ^ (((z)>>4)&7))

// ---------------- scratch ----------------
__device__ float  g_ras[NB*3*VOL];             // (b,c, a0,a1,z)
__device__ float2 g_spec[(size_t)NB*3*128*MLEN]; // (b,c, a0, m=k*128+a1)
__device__ float  g_scalar[2*NB];

// ---------------- rasterize ----------------
__global__ void raster_kernel(const float* __restrict__ V, const float* __restrict__ N) {
    int b = blockIdx.y;
    int p = blockIdx.x*blockDim.x + threadIdx.x;
    const float* Vb = V + (size_t)b*NPTS*3;
    const float* Nb = N + (size_t)b*NPTS*3;
    float* ras = g_ras + (size_t)b*3*VOL;
    float x0 = Vb[3*p+0]*128.f, x1 = Vb[3*p+1]*128.f, x2 = Vb[3*p+2]*128.f;
    float n0 = Nb[3*p+0], n1 = Nb[3*p+1], n2 = Nb[3*p+2];
    float fl0 = floorf(x0), fl1 = floorf(x1), fl2 = floorf(x2);
    int a0 = ((int)fl0)&127, a1 = ((int)fl1)&127, a2 = ((int)fl2)&127;
    int b0 = ((int)ceilf(x0))&127, b1 = ((int)ceilf(x1))&127, b2 = ((int)ceilf(x2))&127;
    float f0 = x0-fl0, f1 = x1-fl1, f2 = x2-fl2;
    #pragma unroll
    for (int c = 0; c < 8; c++) {
        int c0 = (c>>2)&1, c1 = (c>>1)&1, c2 = c&1;
        int i0 = c0 ? b0 : a0;
        int i1 = c1 ? b1 : a1;
        int i2 = c2 ? b2 : a2;
        float w = (c0 ? f0 : 1.f-f0) * (c1 ? f1 : 1.f-f1) * (c2 ? f2 : 1.f-f2);
        int idx = (i0*128 + i1)*128 + i2;
        atomicAdd(&ras[idx],       w*n0);
        atomicAdd(&ras[VOL+idx],   w*n1);
        atomicAdd(&ras[2*VOL+idx], w*n2);
    }
}

// ---------------- register-resident 128-pt FFT (one warp per line) --------
__device__ __forceinline__ float2 cadd(float2 a, float2 b){return make_float2(a.x+b.x, a.y+b.y);}
__device__ __forceinline__ float2 csub(float2 a, float2 b){return make_float2(a.x-b.x, a.y-b.y);}
__device__ __forceinline__ float2 cmul(float2 a, float2 b){return make_float2(a.x*b.x-a.y*b.y, a.x*b.y+a.y*b.x);}

__device__ __forceinline__ void make_tw(float2 tw[7], int lane, float sign) {
    tw[0] = make_float2(1.f, 0.f);
    #pragma unroll
    for (int s = 1; s <= 4; s++) {
        int len = 1<<s;
        float ang = sign*CUDART_PI_F*(float)(lane&(len-1))/(float)len;
        __sincosf(ang, &tw[s].y, &tw[s].x);
    }
    float ang = sign*CUDART_PI_F*(float)lane/32.f;
    __sincosf(ang, &tw[5].y, &tw[5].x);
    ang = sign*CUDART_PI_F*(float)lane/64.f;
    __sincosf(ang, &tw[6].y, &tw[6].x);
}

// DIT, bit-reversed input (element brev7(r*32+lane)), natural order output k=r*32+lane.
__device__ __forceinline__ void fft128_warp(float2 X[4], const float2 tw[7],
                                            int lane, float sign) {
    #pragma unroll
    for (int s = 0; s < 5; s++) {
        int len = 1<<s;
        float2 w = tw[s];
        #pragma unroll
        for (int r = 0; r < 4; r++) {
            float2 x = X[r];
            float2 o;
            o.x = __shfl_xor_sync(0xffffffffu, x.x, len);
            o.y = __shfl_xor_sync(0xffffffffu, x.y, len);
            if ((lane & len) == 0) X[r] = cadd(x, cmul(w, o));
            else                   X[r] = csub(o, cmul(w, x));
        }
    }
    {
        float2 w = tw[5];
        float2 t = cmul(w, X[1]);
        float2 a = cadd(X[0], t), b = csub(X[0], t); X[0]=a; X[1]=b;
        t = cmul(w, X[3]);
        a = cadd(X[2], t); b = csub(X[2], t); X[2]=a; X[3]=b;
    }
    {
        float2 w = tw[6];
        float2 w2 = make_float2(-sign*w.y, sign*w.x);
        float2 t = cmul(w, X[2]);
        float2 a0 = cadd(X[0], t), a2 = csub(X[0], t);
        t = cmul(w2, X[3]);
        float2 a1 = cadd(X[1], t), a3 = csub(X[1], t);
        X[0]=a0; X[1]=a1; X[2]=a2; X[3]=a3;
    }
}

// ---- PassA: fused pack-2 z-r2c + y-fwd per (b,c,a0) plane ----------------
// Packed spectrum P_u (pair a1=2u,2u+1) stored in smem column tau(u)=((u&1)<<5)|(u>>1),
// stride 129. y-phase unpacks on the fly.
__global__ void __launch_bounds__(512) passA() {
    extern __shared__ float2 sh[];          // 64 cols * 129
    int a0 = blockIdx.x, c = blockIdx.y, b = blockIdx.z;
    const float* src = g_ras + ((size_t)(b*3+c)*128 + a0)*16384;
    float2* dspec = g_spec + ((size_t)(b*3+c)*128 + a0)*MLEN;
    int w = threadIdx.x>>5, lane = threadIdx.x&31;
    int q = (int)(__brev((unsigned)lane)>>27);   // brev5(lane)
    int q4 = 4*q;
    float2 tw[7]; make_tw(tw, lane, -1.f);
    // z-phase: 4 packed FFTs per warp (covers two real lines each)
    for (int u = w; u < 64; u += 16) {
        const float* f = src + (2*u)*128;
        const float* g = src + (2*u+1)*128;
        float2 X[4];
        X[0] = make_float2(f[q4+0], g[q4+0]);
        X[1] = make_float2(f[q4+2], g[q4+2]);
        X[2] = make_float2(f[q4+1], g[q4+1]);
        X[3] = make_float2(f[q4+3], g[q4+3]);
        fft128_warp(X, tw, lane, -1.f);
        float2* cp = sh + (((u&1)<<5) | (u>>1))*129;
        cp[lane]    = X[0];
        cp[32+lane] = X[1];
        cp[64+lane] = X[2];
        cp[96+lane] = X[3];
    }
    __syncthreads();
    // y-phase: unpack (Hermitian split) + FFT, direct coalesced global write
    for (int k = w; k < 65; k += 16) {
        int mk = (128 - k) & 127;
        const float2* c0 = sh + q*129;        // tau(2q)
        const float2* c1 = sh + (32+q)*129;   // tau(2q+1)
        float2 pk0 = c0[k], pm0 = c0[mk];
        float2 pk1 = c1[k], pm1 = c1[mk];
        float2 X[4];
        X[0] = make_float2(0.5f*(pk0.x+pm0.x), 0.5f*(pk0.y-pm0.y)); // e=4q+0, a1=2q even part
        X[1] = make_float2(0.5f*(pk1.x+pm1.x), 0.5f*(pk1.y-pm1.y)); // e=4q+2, pair 2q+1 even
        X[2] = make_float2(0.5f*(pk0.y+pm0.y), 0.5f*(pm0.x-pk0.x)); // e=4q+1, pair 2q odd
        X[3] = make_float2(0.5f*(pk1.y+pm1.y), 0.5f*(pm1.x-pk1.x)); // e=4q+3, pair 2q+1 odd
        fft128_warp(X, tw, lane, -1.f);
        float2* dst = dspec + k*128;
        dst[lane]    = X[0];
        dst[32+lane] = X[1];
        dst[64+lane] = X[2];
        dst[96+lane] = X[3];
    }
}

// ---- PassB: fused x-fwd(3ch) + spectral combine + x-inv (ch0) ------------
// meshgrid 'xy' quirk: ch0 multiplier uses a1(jj), ch1 uses a0(e).
__global__ void __launch_bounds__(256) passB() {
    __shared__ float2 sh[3][8][129];
    int m0 = blockIdx.x*8, b = blockIdx.y, tid = threadIdx.x;
    size_t base = (size_t)(b*3)*128*MLEN;
    #pragma unroll
    for (int c = 0; c < 3; c++)
        for (int item = tid; item < 1024; item += 256) {
            int a0 = item>>3, mm = item&7;
            sh[c][mm][SWZ(a0)] = g_spec[base + (size_t)c*128*MLEN + (size_t)a0*MLEN + m0 + mm];
        }
    __syncthreads();
    int w = tid>>5, lane = tid&31;
    int q4 = 4*(int)(__brev((unsigned)lane)>>27);
    float2 tw[7]; make_tw(tw, lane, -1.f);
    float2 A[3][4];
    #pragma unroll
    for (int c = 0; c < 3; c++) {
        A[c][0]=sh[c][w][SWZ(q4+0)]; A[c][1]=sh[c][w][SWZ(q4+2)];
        A[c][2]=sh[c][w][SWZ(q4+1)]; A[c][3]=sh[c][w][SWZ(q4+3)];
        fft128_warp(A[c], tw, lane, -1.f);
    }
    int m = m0 + w;
    int k = m>>7, jj = m&127;
    const float wv = 2.f*CUDART_PI_F/128.f;
    float s_j,c_j,s_k,c_k;
    __sincosf(wv*(float)jj, &s_j, &c_j);
    __sincosf(wv*(float)k,  &s_k, &c_k);
    float m0m = 128.f*s_j, m2m = 128.f*s_k;
    #pragma unroll
    for (int r = 0; r < 4; r++) {
        int e = r*32 + lane;
        float s_i,c_i; __sincosf(wv*(float)e, &s_i, &c_i);
        float m1m = 128.f*s_i;
        float lap = 32768.f*((c_j-1.f)+(c_i-1.f)+(c_k-1.f));
        float dre = -(m0m*A[0][r].y + m1m*A[1][r].y + m2m*A[2][r].y);
        float dimg =  (m0m*A[0][r].x + m1m*A[1][r].x + m2m*A[2][r].x);
        float inv = 1.f/(lap + 1e-6f);
        A[0][r] = make_float2(dre*inv, dimg*inv);
        if ((k|jj|e) == 0) A[0][r] = make_float2(0.f,0.f);
    }
    #pragma unroll
    for (int r = 0; r < 4; r++) sh[0][w][SWZ(r*32+lane)] = A[0][r];
    __syncwarp();
    #pragma unroll
    for (int s = 0; s < 7; s++) tw[s].y = -tw[s].y;   // conjugate -> inverse
    float2 Xo[4];
    Xo[0]=sh[0][w][SWZ(q4+0)]; Xo[1]=sh[0][w][SWZ(q4+2)];
    Xo[2]=sh[0][w][SWZ(q4+1)]; Xo[3]=sh[0][w][SWZ(q4+3)];
    fft128_warp(Xo, tw, lane, +1.f);
    #pragma unroll
    for (int r = 0; r < 4; r++) sh[0][w][SWZ(r*32+lane)] = Xo[r];
    __syncthreads();
    for (int item = tid; item < 1024; item += 256) {
        int a0 = item>>3, mm = item&7;
        g_spec[base + (size_t)a0*MLEN + m0 + mm] = sh[0][mm][SWZ(a0)];
    }
}

// ---- passC1: y-inverse, in place, ch0. One warp per contiguous a1-line ---
__global__ void __launch_bounds__(512) passC1() {
    __shared__ float2 sh[16][129];
    int b = blockIdx.y;
    int tid = threadIdx.x, w = tid>>5, lane = tid&31;
    int l = blockIdx.x*16 + w;          // < 8320
    int a0 = l/65, k = l - a0*65;
    float2* ln = g_spec + ((size_t)(b*3)*128 + a0)*MLEN + k*128;
    int q4 = 4*(int)(__brev((unsigned)lane)>>27);
    float2 tw[7]; make_tw(tw, lane, +1.f);
    #pragma unroll
    for (int r = 0; r < 4; r++) sh[w][SWZ(r*32+lane)] = ln[r*32+lane];
    __syncwarp();
    float2 X[4];
    X[0]=sh[w][SWZ(q4+0)]; X[1]=sh[w][SWZ(q4+2)];
    X[2]=sh[w][SWZ(q4+1)]; X[3]=sh[w][SWZ(q4+3)];
    fft128_warp(X, tw, lane, +1.f);
    #pragma unroll
    for (int r = 0; r < 4; r++) ln[r*32+lane] = X[r];
}

// ---- passC2: pack-2 z-c2r. 32 a1 per block = 16 packed inverse FFTs ------
// C[k] = F_{2u}[k] + i*F_{2u+1}[k], Hermitian-extended; ifft -> (f, g) in (re, im).
__global__ void __launch_bounds__(512) passC2(float* __restrict__ out) {
    __shared__ float2 sh[16][129];       // [packed pair][SWZ(k)]
    int b = blockIdx.y;
    int a0 = blockIdx.x >> 2, t = blockIdx.x & 3;
    int a1base = t*32;
    const float2* sp = g_spec + ((size_t)(b*3)*128 + a0)*MLEN;
    float* o = out + ((size_t)b*128 + a0)*16384;
    int tid = threadIdx.x, w = tid>>5, lane = tid&31;
    for (int item = tid; item < 65*16; item += 512) {
        int k = item>>4, u = item&15;
        float4 v4 = *reinterpret_cast<const float4*>(sp + k*128 + a1base + 2*u);
        // vf=(v4.x,v4.y), vg=(v4.z,v4.w); C[k] = vf + i*vg
        sh[u][SWZ(k)] = make_float2(v4.x - v4.w, v4.y + v4.z);
        if (k >= 1 && k < 64)
            sh[u][SWZ(128-k)] = make_float2(v4.x + v4.w, v4.z - v4.y);
    }
    __syncthreads();
    int q4 = 4*(int)(__brev((unsigned)lane)>>27);
    float2 tw[7]; make_tw(tw, lane, +1.f);
    float2 X[4];
    X[0]=sh[w][SWZ(q4+0)]; X[1]=sh[w][SWZ(q4+2)];
    X[2]=sh[w][SWZ(q4+1)]; X[3]=sh[w][SWZ(q4+3)];
    fft128_warp(X, tw, lane, +1.f);
    const float scale = 1.f/(float)VOL;
    float* o0 = o + (a1base + 2*w)*128;
    float* o1 = o0 + 128;
    o0[lane]    = X[0].x*scale;  o1[lane]    = X[0].y*scale;
    o0[32+lane] = X[1].x*scale;  o1[32+lane] = X[1].y*scale;
    o0[64+lane] = X[2].x*scale;  o1[64+lane] = X[2].y*scale;
    o0[96+lane] = X[3].x*scale;  o1[96+lane] = X[3].y*scale;
}

// ---------------- trilinear gather at points; per-batch sums ----------------
__global__ void interp_kernel(const float* __restrict__ V, const float* __restrict__ out) {
    int b = blockIdx.y;
    int p = blockIdx.x*blockDim.x + threadIdx.x;
    const float* Vb  = V + (size_t)b*NPTS*3;
    const float* phi = out + (size_t)b*VOL;
    float x0 = Vb[3*p+0]*128.f, x1 = Vb[3*p+1]*128.f, x2 = Vb[3*p+2]*128.f;
    float fl0 = floorf(x0), fl1 = floorf(x1), fl2 = floorf(x2);
    int a0 = ((int)fl0)&127, a1 = ((int)fl1)&127, a2 = ((int)fl2)&127;
    int b0 = ((int)ceilf(x0))&127, b1 = ((int)ceilf(x1))&127, b2 = ((int)ceilf(x2))&127;
    float f0 = x0-fl0, f1 = x1-fl1, f2 = x2-fl2;
    float fv = 0.f;
    #pragma unroll
    for (int c = 0; c < 8; c++) {
        int c0 = (c>>2)&1, c1 = (c>>1)&1, c2 = c&1;
        int i0 = c0 ? b0 : a0;
        int i1 = c1 ? b1 : a1;
        int i2 = c2 ? b2 : a2;
        float w = (c0 ? f0 : 1.f-f0) * (c1 ? f1 : 1.f-f1) * (c2 ? f2 : 1.f-f2);
        fv += w * phi[(i0*128 + i1)*128 + i2];
    }
    #pragma unroll
    for (int o = 16; o; o >>= 1) fv += __shfl_down_sync(0xffffffffu, fv, o);
    if ((threadIdx.x & 31) == 0) atomicAdd(&g_scalar[2*b], fv);
    if (p == 0) g_scalar[2*b+1] = phi[0];
}

// ---------------- final normalize in place ----------------
__global__ void norm_kernel(float* __restrict__ out) {
    int b = blockIdx.y;
    int idx = blockIdx.x*blockDim.x + threadIdx.x;
    float* phi = out + (size_t)b*VOL;
    float mean = g_scalar[2*b] * (1.f/(float)NPTS);
    float fv0  = g_scalar[2*b+1] - mean;
    float s = -0.5f / fabsf(fv0);
    phi[idx] = (phi[idx] - mean) * s;
}

// ---------------- host ----------------
extern "C" void kernel_launch(void* const* d_in, const int* in_sizes, int n_in,
                              void* d_out, int out_size) {
    (void)in_sizes; (void)n_in; (void)out_size;
    const float* V = (const float*)d_in[0];
    const float* N = (const float*)d_in[1];
    float* out = (float*)d_out;

    const int PLANE_SMEM = 64*129*sizeof(float2);   // 66,048 B
    cudaFuncSetAttribute(passA, cudaFuncAttributeMaxDynamicSharedMemorySize, PLANE_SMEM);

    void *ras_pv, *sc_pv;
    cudaGetSymbolAddress(&ras_pv, g_ras);
    cudaGetSymbolAddress(&sc_pv,  g_scalar);
    cudaMemsetAsync(ras_pv, 0, (size_t)NB*3*VOL*sizeof(float));
    cudaMemsetAsync(sc_pv,  0, 2*NB*sizeof(float));

    raster_kernel<<<dim3(NPTS/256, NB), 256>>>(V, N);
    passA<<<dim3(128, 3, NB), 512, PLANE_SMEM>>>();
    passB<<<dim3(MLEN/8, NB), 256>>>();
    passC1<<<dim3(8320/16, NB), 512>>>();
    passC2<<<dim3(128*4, NB), 512>>>(out);
    interp_kernel<<<dim3(NPTS/256, NB), 256>>>(V, out);
    norm_kernel<<<dim3(VOL/256, NB), 256>>>(out);
}

// round 17
// speedup vs baseline: 2.4954x; 1.1277x over previous
#include <cuda_runtime.h>
#include <math_constants.h>
#include <cstdint>

#define VOL (128*128*128)
#define KH 65                         // half-spectrum planes along z (rfft)
#define MLEN (KH*128)                 // 8320 spectral (k,a1) entries per a0
#define NPTS 65536
#define NB 4

#define SWZ(z) ((z) ^ (((z)>>4)&7))

// ---------------- scratch ----------------
__device__ float  g_ras[NB*3*VOL];             // (b,c, a0,a1,z)
__device__ float2 g_spec[(size_t)NB*3*128*MLEN]; // (b,c, a0, m=k*128+a1)
__device__ float  g_scalar[2*NB];

// ---------------- rasterize ----------------
__global__ void raster_kernel(const float* __restrict__ V, const float* __restrict__ N) {
    int b = blockIdx.y;
    int p = blockIdx.x*blockDim.x + threadIdx.x;
    const float* Vb = V + (size_t)b*NPTS*3;
    const float* Nb = N + (size_t)b*NPTS*3;
    float* ras = g_ras + (size_t)b*3*VOL;
    float x0 = Vb[3*p+0]*128.f, x1 = Vb[3*p+1]*128.f, x2 = Vb[3*p+2]*128.f;
    float n0 = Nb[3*p+0], n1 = Nb[3*p+1], n2 = Nb[3*p+2];
    float fl0 = floorf(x0), fl1 = floorf(x1), fl2 = floorf(x2);
    int a0 = ((int)fl0)&127, a1 = ((int)fl1)&127, a2 = ((int)fl2)&127;
    int b0 = ((int)ceilf(x0))&127, b1 = ((int)ceilf(x1))&127, b2 = ((int)ceilf(x2))&127;
    float f0 = x0-fl0, f1 = x1-fl1, f2 = x2-fl2;
    #pragma unroll
    for (int c = 0; c < 8; c++) {
        int c0 = (c>>2)&1, c1 = (c>>1)&1, c2 = c&1;
        int i0 = c0 ? b0 : a0;
        int i1 = c1 ? b1 : a1;
        int i2 = c2 ? b2 : a2;
        float w = (c0 ? f0 : 1.f-f0) * (c1 ? f1 : 1.f-f1) * (c2 ? f2 : 1.f-f2);
        int idx = (i0*128 + i1)*128 + i2;
        atomicAdd(&ras[idx],       w*n0);
        atomicAdd(&ras[VOL+idx],   w*n1);
        atomicAdd(&ras[2*VOL+idx], w*n2);
    }
}

// ---------------- register-resident 128-pt FFT (one warp per line) --------
__device__ __forceinline__ float2 cadd(float2 a, float2 b){return make_float2(a.x+b.x, a.y+b.y);}
__device__ __forceinline__ float2 csub(float2 a, float2 b){return make_float2(a.x-b.x, a.y-b.y);}
__device__ __forceinline__ float2 cmul(float2 a, float2 b){return make_float2(a.x*b.x-a.y*b.y, a.x*b.y+a.y*b.x);}

__device__ __forceinline__ void make_tw(float2 tw[7], int lane, float sign) {
    tw[0] = make_float2(1.f, 0.f);
    #pragma unroll
    for (int s = 1; s <= 4; s++) {
        int len = 1<<s;
        float ang = sign*CUDART_PI_F*(float)(lane&(len-1))/(float)len;
        __sincosf(ang, &tw[s].y, &tw[s].x);
    }
    float ang = sign*CUDART_PI_F*(float)lane/32.f;
    __sincosf(ang, &tw[5].y, &tw[5].x);
    ang = sign*CUDART_PI_F*(float)lane/64.f;
    __sincosf(ang, &tw[6].y, &tw[6].x);
}

// DIT, bit-reversed input (element brev7(r*32+lane)), natural order output k=r*32+lane.
__device__ __forceinline__ void fft128_warp(float2 X[4], const float2 tw[7],
                                            int lane, float sign) {
    #pragma unroll
    for (int s = 0; s < 5; s++) {
        int len = 1<<s;
        float2 w = tw[s];
        #pragma unroll
        for (int r = 0; r < 4; r++) {
            float2 x = X[r];
            float2 o;
            o.x = __shfl_xor_sync(0xffffffffu, x.x, len);
            o.y = __shfl_xor_sync(0xffffffffu, x.y, len);
            if ((lane & len) == 0) X[r] = cadd(x, cmul(w, o));
            else                   X[r] = csub(o, cmul(w, x));
        }
    }
    {
        float2 w = tw[5];
        float2 t = cmul(w, X[1]);
        float2 a = cadd(X[0], t), b = csub(X[0], t); X[0]=a; X[1]=b;
        t = cmul(w, X[3]);
        a = cadd(X[2], t); b = csub(X[2], t); X[2]=a; X[3]=b;
    }
    {
        float2 w = tw[6];
        float2 w2 = make_float2(-sign*w.y, sign*w.x);
        float2 t = cmul(w, X[2]);
        float2 a0 = cadd(X[0], t), a2 = csub(X[0], t);
        t = cmul(w2, X[3]);
        float2 a1 = cadd(X[1], t), a3 = csub(X[1], t);
        X[0]=a0; X[1]=a1; X[2]=a2; X[3]=a3;
    }
}

// ---- PassA: fused pack-2 z-r2c + y-fwd per (b,c,a0) plane ----------------
// Packed spectrum P_u (pair a1=2u,2u+1) stored in smem column tau(u)=((u&1)<<5)|(u>>1),
// stride 129. y-phase unpacks on the fly.
__global__ void __launch_bounds__(512) passA() {
    extern __shared__ float2 sh[];          // 64 cols * 129
    int a0 = blockIdx.x, c = blockIdx.y, b = blockIdx.z;
    const float* src = g_ras + ((size_t)(b*3+c)*128 + a0)*16384;
    float2* dspec = g_spec + ((size_t)(b*3+c)*128 + a0)*MLEN;
    int w = threadIdx.x>>5, lane = threadIdx.x&31;
    int q = (int)(__brev((unsigned)lane)>>27);   // brev5(lane)
    int q4 = 4*q;
    float2 tw[7]; make_tw(tw, lane, -1.f);
    // z-phase: 4 packed FFTs per warp (covers two real lines each)
    for (int u = w; u < 64; u += 16) {
        const float* f = src + (2*u)*128;
        const float* g = src + (2*u+1)*128;
        float2 X[4];
        X[0] = make_float2(f[q4+0], g[q4+0]);
        X[1] = make_float2(f[q4+2], g[q4+2]);
        X[2] = make_float2(f[q4+1], g[q4+1]);
        X[3] = make_float2(f[q4+3], g[q4+3]);
        fft128_warp(X, tw, lane, -1.f);
        float2* cp = sh + (((u&1)<<5) | (u>>1))*129;
        cp[lane]    = X[0];
        cp[32+lane] = X[1];
        cp[64+lane] = X[2];
        cp[96+lane] = X[3];
    }
    __syncthreads();
    // y-phase: unpack (Hermitian split) + FFT, direct coalesced global write
    for (int k = w; k < 65; k += 16) {
        int mk = (128 - k) & 127;
        const float2* c0 = sh + q*129;        // tau(2q)
        const float2* c1 = sh + (32+q)*129;   // tau(2q+1)
        float2 pk0 = c0[k], pm0 = c0[mk];
        float2 pk1 = c1[k], pm1 = c1[mk];
        float2 X[4];
        X[0] = make_float2(0.5f*(pk0.x+pm0.x), 0.5f*(pk0.y-pm0.y)); // e=4q+0, a1=2q even part
        X[1] = make_float2(0.5f*(pk1.x+pm1.x), 0.5f*(pk1.y-pm1.y)); // e=4q+2, pair 2q+1 even
        X[2] = make_float2(0.5f*(pk0.y+pm0.y), 0.5f*(pm0.x-pk0.x)); // e=4q+1, pair 2q odd
        X[3] = make_float2(0.5f*(pk1.y+pm1.y), 0.5f*(pm1.x-pk1.x)); // e=4q+3, pair 2q+1 odd
        fft128_warp(X, tw, lane, -1.f);
        float2* dst = dspec + k*128;
        dst[lane]    = X[0];
        dst[32+lane] = X[1];
        dst[64+lane] = X[2];
        dst[96+lane] = X[3];
    }
}

// ---- PassB: x-fwd with ch0/ch2 pre-combined by linearity + combine + x-inv
// DivN = F(m0*s0 + m2*s2) + m1*F(s1): m0(jj), m2(k) are constant per line,
// so channels 0,2 merge during staging -> 2 fwd FFTs + 1 inv instead of 3+1.
// meshgrid 'xy' quirk: ch0 multiplier uses a1(jj), ch1 uses a0(e).
__global__ void __launch_bounds__(256) passB() {
    __shared__ float2 sh[2][8][129];
    int m0 = blockIdx.x*8, b = blockIdx.y, tid = threadIdx.x;
    size_t base = (size_t)(b*3)*128*MLEN;
    const float wv = 2.f*CUDART_PI_F/128.f;
    for (int item = tid; item < 1024; item += 256) {
        int a0 = item>>3, mm = item&7;
        int m = m0 + mm;
        int k = m>>7, jj = m&127;
        size_t off = (size_t)a0*MLEN + m;
        float2 v0 = g_spec[base + off];
        float2 v1 = g_spec[base + (size_t)128*MLEN + off];
        float2 v2 = g_spec[base + (size_t)2*128*MLEN + off];
        float m0m = 128.f*__sinf(wv*(float)jj);
        float m2m = 128.f*__sinf(wv*(float)k);
        sh[0][mm][SWZ(a0)] = make_float2(m0m*v0.x + m2m*v2.x, m0m*v0.y + m2m*v2.y);
        sh[1][mm][SWZ(a0)] = v1;
    }
    __syncthreads();
    int w = tid>>5, lane = tid&31;
    int q4 = 4*(int)(__brev((unsigned)lane)>>27);
    float2 tw[7]; make_tw(tw, lane, -1.f);
    float2 T[4], A1[4];
    T[0]=sh[0][w][SWZ(q4+0)]; T[1]=sh[0][w][SWZ(q4+2)];
    T[2]=sh[0][w][SWZ(q4+1)]; T[3]=sh[0][w][SWZ(q4+3)];
    fft128_warp(T, tw, lane, -1.f);
    A1[0]=sh[1][w][SWZ(q4+0)]; A1[1]=sh[1][w][SWZ(q4+2)];
    A1[2]=sh[1][w][SWZ(q4+1)]; A1[3]=sh[1][w][SWZ(q4+3)];
    fft128_warp(A1, tw, lane, -1.f);
    int m = m0 + w;
    int k = m>>7, jj = m&127;
    float c_j = __cosf(wv*(float)jj);
    float c_k = __cosf(wv*(float)k);
    #pragma unroll
    for (int r = 0; r < 4; r++) {
        int e = r*32 + lane;
        float s_i, c_i; __sincosf(wv*(float)e, &s_i, &c_i);
        float m1m = 128.f*s_i;
        float lap = 32768.f*((c_j-1.f)+(c_i-1.f)+(c_k-1.f));
        float dre = -(T[r].y + m1m*A1[r].y);
        float dimg =  (T[r].x + m1m*A1[r].x);
        float inv = 1.f/(lap + 1e-6f);
        T[r] = make_float2(dre*inv, dimg*inv);
        if ((k|jj|e) == 0) T[r] = make_float2(0.f,0.f);
    }
    #pragma unroll
    for (int r = 0; r < 4; r++) sh[0][w][SWZ(r*32+lane)] = T[r];
    __syncwarp();
    #pragma unroll
    for (int s = 0; s < 7; s++) tw[s].y = -tw[s].y;   // conjugate -> inverse
    float2 Xo[4];
    Xo[0]=sh[0][w][SWZ(q4+0)]; Xo[1]=sh[0][w][SWZ(q4+2)];
    Xo[2]=sh[0][w][SWZ(q4+1)]; Xo[3]=sh[0][w][SWZ(q4+3)];
    fft128_warp(Xo, tw, lane, +1.f);
    #pragma unroll
    for (int r = 0; r < 4; r++) sh[0][w][SWZ(r*32+lane)] = Xo[r];
    __syncthreads();
    for (int item = tid; item < 1024; item += 256) {
        int a0 = item>>3, mm = item&7;
        g_spec[base + (size_t)a0*MLEN + m0 + mm] = sh[0][mm][SWZ(a0)];
    }
}

// ---- passC1: y-inverse, in place, ch0. One warp per contiguous a1-line ---
__global__ void __launch_bounds__(512) passC1() {
    __shared__ float2 sh[16][129];
    int b = blockIdx.y;
    int tid = threadIdx.x, w = tid>>5, lane = tid&31;
    int l = blockIdx.x*16 + w;          // < 8320
    int a0 = l/65, k = l - a0*65;
    float2* ln = g_spec + ((size_t)(b*3)*128 + a0)*MLEN + k*128;
    int q4 = 4*(int)(__brev((unsigned)lane)>>27);
    float2 tw[7]; make_tw(tw, lane, +1.f);
    #pragma unroll
    for (int r = 0; r < 4; r++) sh[w][SWZ(r*32+lane)] = ln[r*32+lane];
    __syncwarp();
    float2 X[4];
    X[0]=sh[w][SWZ(q4+0)]; X[1]=sh[w][SWZ(q4+2)];
    X[2]=sh[w][SWZ(q4+1)]; X[3]=sh[w][SWZ(q4+3)];
    fft128_warp(X, tw, lane, +1.f);
    #pragma unroll
    for (int r = 0; r < 4; r++) ln[r*32+lane] = X[r];
}

// ---- passC2: pack-2 z-c2r. 32 a1 per block = 16 packed inverse FFTs ------
// C[k] = F_{2u}[k] + i*F_{2u+1}[k], Hermitian-extended; ifft -> (f, g) in (re, im).
__global__ void __launch_bounds__(512) passC2(float* __restrict__ out) {
    __shared__ float2 sh[16][129];       // [packed pair][SWZ(k)]
    int b = blockIdx.y;
    int a0 = blockIdx.x >> 2, t = blockIdx.x & 3;
    int a1base = t*32;
    const float2* sp = g_spec + ((size_t)(b*3)*128 + a0)*MLEN;
    float* o = out + ((size_t)b*128 + a0)*16384;
    int tid = threadIdx.x, w = tid>>5, lane = tid&31;
    for (int item = tid; item < 65*16; item += 512) {
        int k = item>>4, u = item&15;
        float4 v4 = *reinterpret_cast<const float4*>(sp + k*128 + a1base + 2*u);
        // vf=(v4.x,v4.y), vg=(v4.z,v4.w); C[k] = vf + i*vg
        sh[u][SWZ(k)] = make_float2(v4.x - v4.w, v4.y + v4.z);
        if (k >= 1 && k < 64)
            sh[u][SWZ(128-k)] = make_float2(v4.x + v4.w, v4.z - v4.y);
    }
    __syncthreads();
    int q4 = 4*(int)(__brev((unsigned)lane)>>27);
    float2 tw[7]; make_tw(tw, lane, +1.f);
    float2 X[4];
    X[0]=sh[w][SWZ(q4+0)]; X[1]=sh[w][SWZ(q4+2)];
    X[2]=sh[w][SWZ(q4+1)]; X[3]=sh[w][SWZ(q4+3)];
    fft128_warp(X, tw, lane, +1.f);
    const float scale = 1.f/(float)VOL;
    float* o0 = o + (a1base + 2*w)*128;
    float* o1 = o0 + 128;
    o0[lane]    = X[0].x*scale;  o1[lane]    = X[0].y*scale;
    o0[32+lane] = X[1].x*scale;  o1[32+lane] = X[1].y*scale;
    o0[64+lane] = X[2].x*scale;  o1[64+lane] = X[2].y*scale;
    o0[96+lane] = X[3].x*scale;  o1[96+lane] = X[3].y*scale;
}

// ---------------- trilinear gather at points; per-batch sums ----------------
__global__ void interp_kernel(const float* __restrict__ V, const float* __restrict__ out) {
    int b = blockIdx.y;
    int p = blockIdx.x*blockDim.x + threadIdx.x;
    const float* Vb  = V + (size_t)b*NPTS*3;
    const float* phi = out + (size_t)b*VOL;
    float x0 = Vb[3*p+0]*128.f, x1 = Vb[3*p+1]*128.f, x2 = Vb[3*p+2]*128.f;
    float fl0 = floorf(x0), fl1 = floorf(x1), fl2 = floorf(x2);
    int a0 = ((int)fl0)&127, a1 = ((int)fl1)&127, a2 = ((int)fl2)&127;
    int b0 = ((int)ceilf(x0))&127, b1 = ((int)ceilf(x1))&127, b2 = ((int)ceilf(x2))&127;
    float f0 = x0-fl0, f1 = x1-fl1, f2 = x2-fl2;
    float fv = 0.f;
    #pragma unroll
    for (int c = 0; c < 8; c++) {
        int c0 = (c>>2)&1, c1 = (c>>1)&1, c2 = c&1;
        int i0 = c0 ? b0 : a0;
        int i1 = c1 ? b1 : a1;
        int i2 = c2 ? b2 : a2;
        float w = (c0 ? f0 : 1.f-f0) * (c1 ? f1 : 1.f-f1) * (c2 ? f2 : 1.f-f2);
        fv += w * phi[(i0*128 + i1)*128 + i2];
    }
    #pragma unroll
    for (int o = 16; o; o >>= 1) fv += __shfl_down_sync(0xffffffffu, fv, o);
    if ((threadIdx.x & 31) == 0) atomicAdd(&g_scalar[2*b], fv);
    if (p == 0) g_scalar[2*b+1] = phi[0];
}

// ---------------- final normalize in place ----------------
__global__ void norm_kernel(float* __restrict__ out) {
    int b = blockIdx.y;
    int idx = blockIdx.x*blockDim.x + threadIdx.x;
    float* phi = out + (size_t)b*VOL;
    float mean = g_scalar[2*b] * (1.f/(float)NPTS);
    float fv0  = g_scalar[2*b+1] - mean;
    float s = -0.5f / fabsf(fv0);
    phi[idx] = (phi[idx] - mean) * s;
}

// ---------------- host ----------------
extern "C" void kernel_launch(void* const* d_in, const int* in_sizes, int n_in,
                              void* d_out, int out_size) {
    (void)in_sizes; (void)n_in; (void)out_size;
    const float* V = (const float*)d_in[0];
    const float* N = (const float*)d_in[1];
    float* out = (float*)d_out;

    const int PLANE_SMEM = 64*129*sizeof(float2);   // 66,048 B
    cudaFuncSetAttribute(passA, cudaFuncAttributeMaxDynamicSharedMemorySize, PLANE_SMEM);

    void *ras_pv, *sc_pv;
    cudaGetSymbolAddress(&ras_pv, g_ras);
    cudaGetSymbolAddress(&sc_pv,  g_scalar);
    cudaMemsetAsync(ras_pv, 0, (size_t)NB*3*VOL*sizeof(float));
    cudaMemsetAsync(sc_pv,  0, 2*NB*sizeof(float));

    raster_kernel<<<dim3(NPTS/256, NB), 256>>>(V, N);
    passA<<<dim3(128, 3, NB), 512, PLANE_SMEM>>>();
    passB<<<dim3(MLEN/8, NB), 256>>>();
    passC1<<<dim3(8320/16, NB), 512>>>();
    passC2<<<dim3(128*4, NB), 512>>>(out);
    interp_kernel<<<dim3(NPTS/256, NB), 256>>>(V, out);
    norm_kernel<<<dim3(VOL/256, NB), 256>>>(out);
}